// round 7
// baseline (speedup 1.0000x reference)
#include <cuda_runtime.h>
#include <cuda_fp16.h>
#include <cstdint>

#define SPX 3136      // 56*56
#define BATCH 8
#define DIM 256
#define DIM2 512
#define ROWS_TOT (BATCH * SPX)   // 25088 = 196 * 128

// ---------------- scratch (static __device__, allocation-free) ----------------
__device__ __half g_xTh[(size_t)ROWS_TOT * DIM];     // fp16(x^T) [B*S, 256]
__device__ __half g_cath[(size_t)ROWS_TOT * DIM2];   // [B*S, 512] = [h | xj]
__device__ __half g_gh[(size_t)ROWS_TOT * DIM2];     // gelu out [B*S, 512]
__device__ __half g_w1h[(size_t)DIM * DIM];          // fp16(w1) [256,256]
__device__ __half g_wgh[(size_t)DIM2 * DIM2];        // fp16(wg) [512,512]
__device__ __half g_w2h[(size_t)DIM * DIM2];         // fp16(w2) [256,512]
__device__ float g_cm1[(size_t)BATCH * 56 * 2 * DIM], g_cm2[(size_t)BATCH * 56 * 2 * DIM];
__device__ float g_sc1[DIM], g_sh1[DIM];
__device__ float g_scg[DIM2], g_shg[DIM2];
__device__ float g_sc2[DIM], g_sh2[DIM];

// ---------------- PTX helpers (sm_80-generic only) ----------------
__device__ __forceinline__ uint32_t smem_u32(const void* p) {
    uint32_t a;
    asm("{ .reg .u64 t; cvta.to.shared.u64 t, %1; cvt.u32.u64 %0, t; }" : "=r"(a) : "l"(p));
    return a;
}
#define CP_ASYNC16(sm, gm) \
    asm volatile("cp.async.cg.shared.global [%0], [%1], 16;" :: "r"(sm), "l"(gm) : "memory")
#define CP_COMMIT() asm volatile("cp.async.commit_group;" ::: "memory")
#define CP_WAIT1() asm volatile("cp.async.wait_group 1;" ::: "memory")
#define CP_WAIT0() asm volatile("cp.async.wait_group 0;" ::: "memory")
#define LDSM_X4(r0, r1, r2, r3, addr)                                        \
    asm volatile("ldmatrix.sync.aligned.m8n8.x4.shared.b16 {%0,%1,%2,%3}, [%4];" \
                 : "=r"(r0), "=r"(r1), "=r"(r2), "=r"(r3) : "r"(addr))

__device__ __forceinline__ void mma_fp16(float* d, const uint32_t* a, const uint32_t* b) {
    asm volatile(
        "mma.sync.aligned.m16n8k16.row.col.f32.f16.f16.f32 "
        "{%0,%1,%2,%3}, {%4,%5,%6,%7}, {%8,%9}, {%0,%1,%2,%3};"
        : "+f"(d[0]), "+f"(d[1]), "+f"(d[2]), "+f"(d[3])
        : "r"(a[0]), "r"(a[1]), "r"(a[2]), "r"(a[3]), "r"(b[0]), "r"(b[1]));
}

// ---------------- fused prep + weight packing ----------------
__global__ void prep_pack(const float* __restrict__ w1, const float* __restrict__ wg,
                          const float* __restrict__ w2,
                          const float* __restrict__ b1, const float* __restrict__ g1,
                          const float* __restrict__ be1, const float* __restrict__ m1,
                          const float* __restrict__ v1,
                          const float* __restrict__ bg, const float* __restrict__ gg,
                          const float* __restrict__ beg, const float* __restrict__ mg,
                          const float* __restrict__ vg,
                          const float* __restrict__ b2, const float* __restrict__ g2,
                          const float* __restrict__ be2, const float* __restrict__ m2,
                          const float* __restrict__ v2) {
    int blk = blockIdx.x;
    if (blk < 1792) {
        int idx = blk * 256 + threadIdx.x;
        if (idx < 65536) {
            g_w1h[idx] = __float2half_rn(w1[idx]);
        } else if (idx < 65536 + 262144) {
            int j = idx - 65536;
            g_wgh[j] = __float2half_rn(wg[j]);
        } else {
            int j = idx - 65536 - 262144;
            g_w2h[j] = __float2half_rn(w2[j]);
        }
        return;
    }
    int i = threadIdx.x;
    {
        float s = g1[i] / sqrtf(v1[i] + 1e-5f);
        g_sc1[i] = s; g_sh1[i] = (b1[i] - m1[i]) * s + be1[i];
        float s2 = g2[i] / sqrtf(v2[i] + 1e-5f);
        g_sc2[i] = s2; g_sh2[i] = (b2[i] - m2[i]) * s2 + be2[i];
    }
#pragma unroll
    for (int r = 0; r < 2; r++) {
        int j = i + r * 256;
        float sg = gg[j] / sqrtf(vg[j] + 1e-5f);
        g_scg[j] = sg; g_shg[j] = (bg[j] - mg[j]) * sg + beg[j];
    }
}

// ---------------- transpose x [B,256,S] -> fp16 [B*S, 256] ----------------
__global__ void __launch_bounds__(256) transpose_in_pack(const float* __restrict__ x) {
    __shared__ float t[32][33];
    int tx = threadIdx.x & 31, ty = threadIdx.x >> 5;
    int s0 = blockIdx.x * 32, c0 = blockIdx.y * 32, b = blockIdx.z;
    const float* xp = x + ((size_t)b * DIM + c0) * SPX + s0;
    for (int i = ty; i < 32; i += 8) t[i][tx] = xp[(size_t)i * SPX + tx];
    __syncthreads();
    __half* op = g_xTh + ((size_t)(b * SPX + s0)) * DIM + c0;
    for (int i = ty; i < 32; i += 8)
        op[(size_t)i * DIM + tx] = __float2half_rn(t[tx][i]);
}

// ---------------- MRConv4d (R5 versions: 256 threads, latency-tolerant) ----------------
__global__ void __launch_bounds__(256) colmin_kernel() {
    int x = blockIdx.x, b = blockIdx.y, c = threadIdx.x;
    const __half* base = g_cath + ((size_t)b * SPX) * DIM2 + c;
    float a1e = 1e30f, a2e = 1e30f, a1o = 1e30f, a2o = 1e30f;
    for (int y = 0; y < 56; y += 2) {
        float v = __half2float(base[(size_t)(y * 56 + x) * DIM2]);
        if (v < a1e) { a2e = a1e; a1e = v; } else if (v < a2e) a2e = v;
        float w = __half2float(base[(size_t)((y + 1) * 56 + x) * DIM2]);
        if (w < a1o) { a2o = a1o; a1o = w; } else if (w < a2o) a2o = w;
    }
    size_t o = ((size_t)(b * 56 + x) * 2) * DIM + c;
    g_cm1[o] = a1e; g_cm2[o] = a2e;
    g_cm1[o + DIM] = a1o; g_cm2[o + DIM] = a2o;
}

__global__ void __launch_bounds__(256) row_combine_kernel() {
    int y = blockIdx.x, b = blockIdx.y, c = threadIdx.x;
    const __half* base = g_cath + ((size_t)(b * SPX + y * 56)) * DIM2 + c;
    float r1e = 1e30f, r2e = 1e30f, r1o = 1e30f, r2o = 1e30f;
    float hv[56];
    for (int x = 0; x < 56; x += 2) {
        float v = __half2float(base[(size_t)x * DIM2]);
        hv[x] = v;
        if (v < r1e) { r2e = r1e; r1e = v; } else if (v < r2e) r2e = v;
        float w = __half2float(base[(size_t)(x + 1) * DIM2]);
        hv[x + 1] = w;
        if (w < r1o) { r2o = r1o; r1o = w; } else if (w < r2o) r2o = w;
    }
    int py = y & 1;
    __half* ob = g_cath + ((size_t)(b * SPX + y * 56)) * DIM2 + DIM + c;
    for (int x = 0; x < 56; x++) {
        float v = hv[x];
        size_t o = ((size_t)(b * 56 + x) * 2 + py) * DIM + c;
        float c1 = g_cm1[o], c2 = g_cm2[o];
        float ec = (v == c1) ? c2 : c1;
        float m1r = (x & 1) ? r1o : r1e, m2r = (x & 1) ? r2o : r2e;
        float er = (v == m1r) ? m2r : m1r;
        ob[(size_t)x * DIM2] = __float2half_rn(fmaxf(0.0f, v - fminf(ec, er)));
    }
}

// ---------------- fp16 mma.sync GEMM: CTA 128x128, 4 warps of 64x64, BK=64 ----------------
// 128 threads, 2 CTAs/SM, double-buffered cp.async.
// Per k16-step: 8 ldsm.x4 per warp for 32 MMAs (0.25 ldsm/MMA -> smem/MMA balanced).
// MODE 0: BN -> fp16, row stride 512 (fc1)
// MODE 1: BN + exact GELU -> fp16, row stride 512 (gemm2)
// MODE 2: BN + residual -> transposed fp32 out[B,256,S] via 128x129 staged transpose
#define GSMEM 66560
template <int MODE>
__global__ void __launch_bounds__(128, 2)
fp16_gemm(const __half* __restrict__ Ag, const __half* __restrict__ Wg,
          void* __restrict__ dstv, const float* __restrict__ xres,
          const float* __restrict__ scale, const float* __restrict__ shift, int K) {
    extern __shared__ __align__(1024) char smem[];
    __shared__ float s_scale[128], s_shift[128];
    const int tid = threadIdx.x, lane = tid & 31, wid = tid >> 5;  // 4 warps
    const int warp_m = wid >> 1, warp_n = wid & 1;                 // 2x2
    const int r0 = blockIdx.x * 128, n0 = blockIdx.y * 128;
    const uint32_t sb = smem_u32(smem);
    s_scale[tid] = scale[n0 + tid];
    s_shift[tid] = shift[n0 + tid];

    // loader: each thread owns one row (128 rows), 8 x 16B chunks per row
    const uint32_t lswb = tid * 128;
    const size_t aoffs = (size_t)(r0 + tid) * K;
    const size_t boffs = (size_t)(n0 + tid) * K;

    // ldmatrix lane bases
    const int rA = (lane & 7) + ((lane >> 3) & 1) * 8;
    const int kcA = lane >> 4;
    const int rB = (lane & 7) + ((lane >> 4) & 1) * 8;
    const int kcB = (lane >> 3) & 1;

    float acc[4][8][4];
#pragma unroll
    for (int a = 0; a < 4; a++)
#pragma unroll
        for (int b = 0; b < 8; b++)
#pragma unroll
            for (int i = 0; i < 4; i++) acc[a][b][i] = 0.0f;

    const int NS = K >> 6;

    // prologue: stage 0 -> buf 0 (A at +0 [16KB], B at +16384 [16KB], stage stride 32768)
#pragma unroll
    for (int c = 0; c < 8; c++) {
        uint32_t sw = lswb + ((c ^ (tid & 7)) << 4);
        CP_ASYNC16(sb + sw, Ag + aoffs + c * 8);
        CP_ASYNC16(sb + 16384 + sw, Wg + boffs + c * 8);
    }
    CP_COMMIT();

    for (int s = 0; s < NS; s++) {
        const int buf = s & 1;
        if (s + 1 < NS) {
            const uint32_t nb = sb + (buf ^ 1) * 32768;
            const size_t kadd = (size_t)(s + 1) * 64;
#pragma unroll
            for (int c = 0; c < 8; c++) {
                uint32_t sw = lswb + ((c ^ (tid & 7)) << 4);
                CP_ASYNC16(nb + sw, Ag + aoffs + kadd + c * 8);
                CP_ASYNC16(nb + 16384 + sw, Wg + boffs + kadd + c * 8);
            }
            CP_COMMIT();
            CP_WAIT1();
        } else {
            CP_WAIT0();
        }
        __syncthreads();

        const uint32_t aBase = sb + buf * 32768;
        const uint32_t bBase = aBase + 16384;
#pragma unroll
        for (int kk = 0; kk < 4; kk++) {
            uint32_t af[4][4];
#pragma unroll
            for (int mf = 0; mf < 4; mf++) {
                int row = warp_m * 64 + mf * 16 + rA;
                uint32_t addr = aBase + row * 128 + (((kk * 2 + kcA) ^ (row & 7)) << 4);
                LDSM_X4(af[mf][0], af[mf][1], af[mf][2], af[mf][3], addr);
            }
            uint32_t bf[4][4];
#pragma unroll
            for (int nb2 = 0; nb2 < 4; nb2++) {
                int row = warp_n * 64 + nb2 * 16 + rB;
                uint32_t addr = bBase + row * 128 + (((kk * 2 + kcB) ^ (row & 7)) << 4);
                LDSM_X4(bf[nb2][0], bf[nb2][1], bf[nb2][2], bf[nb2][3], addr);
            }
#pragma unroll
            for (int mf = 0; mf < 4; mf++)
#pragma unroll
                for (int nf = 0; nf < 8; nf++)
                    mma_fp16(acc[mf][nf], af[mf], &bf[nf >> 1][(nf & 1) * 2]);
        }
        __syncthreads();
    }

    // ---------------- epilogue ----------------
    if (MODE == 2) {
        float* stg = (float*)smem;  // 128 x 129 fp32 staging (~66 KB)
        float* out = (float*)dstv;
        // all 4 warps stage their disjoint 64x64 blocks
#pragma unroll
        for (int mf = 0; mf < 4; mf++)
#pragma unroll
            for (int nf = 0; nf < 8; nf++)
#pragma unroll
                for (int half = 0; half < 2; half++) {
                    int rl = warp_m * 64 + mf * 16 + (lane >> 2) + half * 8;
                    int cl = warp_n * 64 + nf * 8 + (lane & 3) * 2;
                    stg[rl * 129 + cl] =
                        fmaf(acc[mf][nf][half * 2 + 0], s_scale[cl], s_shift[cl]);
                    stg[rl * 129 + cl + 1] =
                        fmaf(acc[mf][nf][half * 2 + 1], s_scale[cl + 1], s_shift[cl + 1]);
                }
        __syncthreads();
#pragma unroll
        for (int cc = 0; cc < 32; cc++) {
            int c = wid * 32 + cc;
#pragma unroll
            for (int j = 0; j < 4; j++) {
                int i = lane + 32 * j;
                int r = r0 + i;
                int b = r / SPX;
                size_t o = ((size_t)(b * DIM + n0 + c)) * SPX + (r - b * SPX);
                out[o] = stg[i * 129 + c] + xres[o];
            }
        }
        return;
    }

    const int mw = r0 + warp_m * 64;
    const int nw = warp_n * 64;
    __half* dp_base = (__half*)dstv;
#pragma unroll
    for (int mf = 0; mf < 4; mf++) {
#pragma unroll
        for (int nf = 0; nf < 8; nf++) {
#pragma unroll
            for (int half = 0; half < 2; half++) {
                int grow = mw + mf * 16 + (lane >> 2) + half * 8;
                int lcol = nw + nf * 8 + (lane & 3) * 2;
                float v0 = fmaf(acc[mf][nf][half * 2 + 0], s_scale[lcol], s_shift[lcol]);
                float v1 = fmaf(acc[mf][nf][half * 2 + 1], s_scale[lcol + 1], s_shift[lcol + 1]);
                if (MODE == 1) {
                    v0 = 0.5f * v0 * (1.0f + erff(v0 * 0.70710678118654752f));
                    v1 = 0.5f * v1 * (1.0f + erff(v1 * 0.70710678118654752f));
                }
                __half2 hp;
                hp.x = __float2half_rn(v0);
                hp.y = __float2half_rn(v1);
                *(__half2*)(dp_base + (size_t)grow * DIM2 + n0 + lcol) = hp;
            }
        }
    }
}

// ---------------------------------------------------------------------------
extern "C" void kernel_launch(void* const* d_in, const int* in_sizes, int n_in,
                              void* d_out, int out_size) {
    const float* x   = (const float*)d_in[0];
    const float* w1  = (const float*)d_in[1];
    const float* b1  = (const float*)d_in[2];
    const float* g1  = (const float*)d_in[3];
    const float* be1 = (const float*)d_in[4];
    const float* m1  = (const float*)d_in[5];
    const float* v1  = (const float*)d_in[6];
    const float* wg  = (const float*)d_in[7];
    const float* bg  = (const float*)d_in[8];
    const float* gg  = (const float*)d_in[9];
    const float* beg = (const float*)d_in[10];
    const float* mg  = (const float*)d_in[11];
    const float* vg  = (const float*)d_in[12];
    const float* w2  = (const float*)d_in[13];
    const float* b2  = (const float*)d_in[14];
    const float* g2  = (const float*)d_in[15];
    const float* be2 = (const float*)d_in[16];
    const float* m2  = (const float*)d_in[17];
    const float* v2  = (const float*)d_in[18];

    __half *xTh, *cath, *gh, *w1h, *wgh, *w2h;
    float *sc1, *sh1, *scg, *shg, *sc2, *sh2;
    cudaGetSymbolAddress((void**)&xTh, g_xTh);
    cudaGetSymbolAddress((void**)&cath, g_cath);
    cudaGetSymbolAddress((void**)&gh, g_gh);
    cudaGetSymbolAddress((void**)&w1h, g_w1h);
    cudaGetSymbolAddress((void**)&wgh, g_wgh);
    cudaGetSymbolAddress((void**)&w2h, g_w2h);
    cudaGetSymbolAddress((void**)&sc1, g_sc1);
    cudaGetSymbolAddress((void**)&sh1, g_sh1);
    cudaGetSymbolAddress((void**)&scg, g_scg);
    cudaGetSymbolAddress((void**)&shg, g_shg);
    cudaGetSymbolAddress((void**)&sc2, g_sc2);
    cudaGetSymbolAddress((void**)&sh2, g_sh2);

    cudaFuncSetAttribute(fp16_gemm<0>, cudaFuncAttributeMaxDynamicSharedMemorySize, GSMEM);
    cudaFuncSetAttribute(fp16_gemm<1>, cudaFuncAttributeMaxDynamicSharedMemorySize, GSMEM);
    cudaFuncSetAttribute(fp16_gemm<2>, cudaFuncAttributeMaxDynamicSharedMemorySize, GSMEM);

    prep_pack<<<1793, 256>>>(w1, wg, w2, b1, g1, be1, m1, v1,
                             bg, gg, beg, mg, vg, b2, g2, be2, m2, v2);
    transpose_in_pack<<<dim3(98, 8, 8), 256>>>(x);

    // fc1: cat[:, 0:256] = fp16(BN(x @ w1^T))
    fp16_gemm<0><<<dim3(196, 2), 128, GSMEM>>>(xTh, w1h, cath, nullptr, sc1, sh1, DIM);
    // MRConv4d -> cat[:, 256:512]
    colmin_kernel<<<dim3(56, 8), 256>>>();
    row_combine_kernel<<<dim3(56, 8), 256>>>();
    // g = fp16(GELU(BN(cat @ wg^T)))
    fp16_gemm<1><<<dim3(196, 4), 128, GSMEM>>>(cath, wgh, gh, nullptr, scg, shg, DIM2);
    // out[B,256,S] = BN(g @ w2^T)^T + x  (fused transpose + residual)
    fp16_gemm<2><<<dim3(196, 2), 128, GSMEM>>>(gh, w2h, d_out, x, sc2, sh2, DIM2);
}

// round 8
// speedup vs baseline: 1.5420x; 1.5420x over previous
#include <cuda_runtime.h>
#include <cuda_fp16.h>
#include <cstdint>

#define SPX 3136      // 56*56
#define BATCH 8
#define DIM 256
#define DIM2 512
#define ROWS_TOT (BATCH * SPX)   // 25088 = 196 * 128

// ---------------- scratch (static __device__, allocation-free) ----------------
__device__ __half g_xTh[(size_t)ROWS_TOT * DIM];     // fp16(x^T) [B*S, 256]
__device__ __half g_cath[(size_t)ROWS_TOT * DIM2];   // [B*S, 512] = [h | xj]
__device__ __half g_gh[(size_t)ROWS_TOT * DIM2];     // gelu out [B*S, 512]
__device__ __half g_w1h[(size_t)DIM * DIM];          // fp16(w1) [256,256]
__device__ __half g_wgh[(size_t)DIM2 * DIM2];        // fp16(wg) [512,512]
__device__ __half g_w2h[(size_t)DIM * DIM2];         // fp16(w2) [256,512]
__device__ float g_cm1[(size_t)BATCH * 56 * 2 * DIM], g_cm2[(size_t)BATCH * 56 * 2 * DIM];
__device__ float g_sc1[DIM], g_sh1[DIM];
__device__ float g_scg[DIM2], g_shg[DIM2];
__device__ float g_sc2[DIM], g_sh2[DIM];

// ---------------- PTX helpers (sm_80-generic only) ----------------
__device__ __forceinline__ uint32_t smem_u32(const void* p) {
    uint32_t a;
    asm("{ .reg .u64 t; cvta.to.shared.u64 t, %1; cvt.u32.u64 %0, t; }" : "=r"(a) : "l"(p));
    return a;
}
#define CP_ASYNC16(sm, gm) \
    asm volatile("cp.async.cg.shared.global [%0], [%1], 16;" :: "r"(sm), "l"(gm) : "memory")
#define CP_COMMIT() asm volatile("cp.async.commit_group;" ::: "memory")
#define CP_WAIT2() asm volatile("cp.async.wait_group 2;" ::: "memory")
#define CP_WAIT1() asm volatile("cp.async.wait_group 1;" ::: "memory")
#define CP_WAIT0() asm volatile("cp.async.wait_group 0;" ::: "memory")
#define LDSM_X4(r0, r1, r2, r3, addr)                                        \
    asm volatile("ldmatrix.sync.aligned.m8n8.x4.shared.b16 {%0,%1,%2,%3}, [%4];" \
                 : "=r"(r0), "=r"(r1), "=r"(r2), "=r"(r3) : "r"(addr))

__device__ __forceinline__ void mma_fp16(float* d, const uint32_t* a, const uint32_t* b) {
    asm volatile(
        "mma.sync.aligned.m16n8k16.row.col.f32.f16.f16.f32 "
        "{%0,%1,%2,%3}, {%4,%5,%6,%7}, {%8,%9}, {%0,%1,%2,%3};"
        : "+f"(d[0]), "+f"(d[1]), "+f"(d[2]), "+f"(d[3])
        : "r"(a[0]), "r"(a[1]), "r"(a[2]), "r"(a[3]), "r"(b[0]), "r"(b[1]));
}

// two-smallest update / merge (exact exclude-self min machinery)
__device__ __forceinline__ void ts_upd(float& m1, float& m2, float v) {
    if (v < m1) { m2 = m1; m1 = v; } else if (v < m2) { m2 = v; }
}
__device__ __forceinline__ void ts_merge(float a1, float a2, float b1, float b2,
                                         float& r1, float& r2) {
    r1 = fminf(a1, b1);
    r2 = fminf(fmaxf(a1, b1), fminf(a2, b2));
}

// ---------------- fused prep + weight packing ----------------
__global__ void prep_pack(const float* __restrict__ w1, const float* __restrict__ wg,
                          const float* __restrict__ w2,
                          const float* __restrict__ b1, const float* __restrict__ g1,
                          const float* __restrict__ be1, const float* __restrict__ m1,
                          const float* __restrict__ v1,
                          const float* __restrict__ bg, const float* __restrict__ gg,
                          const float* __restrict__ beg, const float* __restrict__ mg,
                          const float* __restrict__ vg,
                          const float* __restrict__ b2, const float* __restrict__ g2,
                          const float* __restrict__ be2, const float* __restrict__ m2,
                          const float* __restrict__ v2) {
    int blk = blockIdx.x;
    if (blk < 1792) {
        int idx = blk * 256 + threadIdx.x;
        if (idx < 65536) {
            g_w1h[idx] = __float2half_rn(w1[idx]);
        } else if (idx < 65536 + 262144) {
            int j = idx - 65536;
            g_wgh[j] = __float2half_rn(wg[j]);
        } else {
            int j = idx - 65536 - 262144;
            g_w2h[j] = __float2half_rn(w2[j]);
        }
        return;
    }
    int i = threadIdx.x;
    {
        float s = g1[i] / sqrtf(v1[i] + 1e-5f);
        g_sc1[i] = s; g_sh1[i] = (b1[i] - m1[i]) * s + be1[i];
        float s2 = g2[i] / sqrtf(v2[i] + 1e-5f);
        g_sc2[i] = s2; g_sh2[i] = (b2[i] - m2[i]) * s2 + be2[i];
    }
#pragma unroll
    for (int r = 0; r < 2; r++) {
        int j = i + r * 256;
        float sg = gg[j] / sqrtf(vg[j] + 1e-5f);
        g_scg[j] = sg; g_shg[j] = (bg[j] - mg[j]) * sg + beg[j];
    }
}

// ---------------- transpose x [B,256,S] -> fp16 [B*S, 256] ----------------
__global__ void __launch_bounds__(256) transpose_in_pack(const float* __restrict__ x) {
    __shared__ float t[32][33];
    int tx = threadIdx.x & 31, ty = threadIdx.x >> 5;
    int s0 = blockIdx.x * 32, c0 = blockIdx.y * 32, b = blockIdx.z;
    const float* xp = x + ((size_t)b * DIM + c0) * SPX + s0;
    for (int i = ty; i < 32; i += 8) t[i][tx] = xp[(size_t)i * SPX + tx];
    __syncthreads();
    __half* op = g_xTh + ((size_t)(b * SPX + s0)) * DIM + c0;
    for (int i = ty; i < 32; i += 8)
        op[(size_t)i * DIM + tx] = __float2half_rn(t[tx][i]);
}

// ---------------- MRConv4d: column pass, 256 threads, 4-way unrolled (MLP=4) ----------------
__global__ void __launch_bounds__(256) colmin_kernel() {
    int x = blockIdx.x, b = blockIdx.y, c = threadIdx.x;
    const __half* base = g_cath + ((size_t)b * SPX) * DIM2 + c;
    float m1[4], m2[4];
#pragma unroll
    for (int q = 0; q < 4; q++) { m1[q] = 1e30f; m2[q] = 1e30f; }
    for (int y4 = 0; y4 < 14; y4++) {
        float v[4];
#pragma unroll
        for (int q = 0; q < 4; q++)
            v[q] = __half2float(__ldg(&base[(size_t)((y4 * 4 + q) * 56 + x) * DIM2]));
#pragma unroll
        for (int q = 0; q < 4; q++) ts_upd(m1[q], m2[q], v[q]);
    }
    float e1, e2, o1, o2;
    ts_merge(m1[0], m2[0], m1[2], m2[2], e1, e2);
    ts_merge(m1[1], m2[1], m1[3], m2[3], o1, o2);
    size_t o = ((size_t)(b * 56 + x) * 2) * DIM + c;
    g_cm1[o] = e1; g_cm2[o] = e2;
    g_cm1[o + DIM] = o1; g_cm2[o + DIM] = o2;
}

// ---------------- MRConv4d: row pass + combine -> xj (4-way unrolled loads) ----------------
__global__ void __launch_bounds__(256) row_combine_kernel() {
    int y = blockIdx.x, b = blockIdx.y, c = threadIdx.x;
    const __half* base = g_cath + ((size_t)(b * SPX + y * 56)) * DIM2 + c;
    float m1[4], m2[4];
#pragma unroll
    for (int q = 0; q < 4; q++) { m1[q] = 1e30f; m2[q] = 1e30f; }
    float hv[56];
    for (int x4 = 0; x4 < 14; x4++) {
        float v[4];
#pragma unroll
        for (int q = 0; q < 4; q++)
            v[q] = __half2float(__ldg(&base[(size_t)(x4 * 4 + q) * DIM2]));
#pragma unroll
        for (int q = 0; q < 4; q++) {
            hv[x4 * 4 + q] = v[q];
            ts_upd(m1[q], m2[q], v[q]);
        }
    }
    float e1, e2, o1, o2;
    ts_merge(m1[0], m2[0], m1[2], m2[2], e1, e2);
    ts_merge(m1[1], m2[1], m1[3], m2[3], o1, o2);

    int py = y & 1;
    __half* ob = g_cath + ((size_t)(b * SPX + y * 56)) * DIM2 + DIM + c;
    const size_t cmb = ((size_t)(b * 56) * 2 + py) * DIM + c;
    for (int x = 0; x < 56; x++) {
        float v = hv[x];
        size_t o = cmb + (size_t)x * 2 * DIM;
        float c1 = g_cm1[o], c2 = g_cm2[o];
        float ec = (v == c1) ? c2 : c1;
        float r1 = (x & 1) ? o1 : e1, r2 = (x & 1) ? o2 : e2;
        float er = (v == r1) ? r2 : r1;
        ob[(size_t)x * DIM2] = __float2half_rn(fmaxf(0.0f, v - fminf(ec, er)));
    }
}

// ---------------- fp16 mma.sync GEMM (R5 shape, 3-stage cp.async) ----------------
// CTA 128x128, 8 warps (2m x 4n) of 64x32, BK=64, 256 threads, 2 CTAs/SM.
// MODE 0: BN -> fp16, row stride 512 (fc1)
// MODE 1: BN + exact GELU -> fp16, row stride 512 (gemm2)
// MODE 2: BN + residual -> transposed fp32 out[B,256,S] via 128x129 staged transpose
#define GSMEM 98304
template <int MODE>
__global__ void __launch_bounds__(256, 2)
fp16_gemm(const __half* __restrict__ Ag, const __half* __restrict__ Wg,
          void* __restrict__ dstv, const float* __restrict__ xres,
          const float* __restrict__ scale, const float* __restrict__ shift, int K) {
    extern __shared__ __align__(1024) char smem[];
    __shared__ float s_scale[128], s_shift[128];
    const int tid = threadIdx.x, lane = tid & 31, wid = tid >> 5;
    const int warp_m = wid >> 2, warp_n = wid & 3;
    const int r0 = blockIdx.x * 128, n0 = blockIdx.y * 128;
    const uint32_t sb = smem_u32(smem);
    if (tid < 128) { s_scale[tid] = scale[n0 + tid]; s_shift[tid] = shift[n0 + tid]; }

    uint32_t loff[4];
    size_t aoff[4], boff[4];
#pragma unroll
    for (int i = 0; i < 4; i++) {
        int idx = tid + i * 256;
        int row = idx >> 3, c = idx & 7;
        loff[i] = row * 128 + ((c ^ (row & 7)) << 4);
        aoff[i] = (size_t)(r0 + row) * K + c * 8;
        boff[i] = (size_t)(n0 + row) * K + c * 8;
    }

    const int rowA[4] = {warp_m * 64 + 0 * 16 + (lane & 7) + ((lane >> 3) & 1) * 8,
                         warp_m * 64 + 1 * 16 + (lane & 7) + ((lane >> 3) & 1) * 8,
                         warp_m * 64 + 2 * 16 + (lane & 7) + ((lane >> 3) & 1) * 8,
                         warp_m * 64 + 3 * 16 + (lane & 7) + ((lane >> 3) & 1) * 8};
    const int kcA = lane >> 4;
    const int rowB[2] = {warp_n * 32 + 0 * 16 + (lane & 7) + ((lane >> 4) & 1) * 8,
                         warp_n * 32 + 1 * 16 + (lane & 7) + ((lane >> 4) & 1) * 8};
    const int kcB = (lane >> 3) & 1;

    float acc[4][4][4];
#pragma unroll
    for (int a = 0; a < 4; a++)
#pragma unroll
        for (int b = 0; b < 4; b++)
#pragma unroll
            for (int i = 0; i < 4; i++) acc[a][b][i] = 0.0f;

    const int NS = K >> 6;

    // prologue: load stages 0,1 into bufs 0,1 (32 KB per stage, 3 bufs)
#pragma unroll
    for (int st = 0; st < 2; st++) {
        const uint32_t bbuf = sb + st * 32768;
        const size_t kadd = (size_t)st * 64;
#pragma unroll
        for (int i = 0; i < 4; i++) {
            CP_ASYNC16(bbuf + loff[i], Ag + aoff[i] + kadd);
            CP_ASYNC16(bbuf + 16384 + loff[i], Wg + boff[i] + kadd);
        }
        CP_COMMIT();
    }

    int buf = 0;
    for (int s = 0; s < NS; s++) {
        if (s + 2 < NS) {
            int nb_i = (buf + 2) % 3;
            const uint32_t nb = sb + nb_i * 32768;
            const size_t kadd = (size_t)(s + 2) * 64;
#pragma unroll
            for (int i = 0; i < 4; i++) {
                CP_ASYNC16(nb + loff[i], Ag + aoff[i] + kadd);
                CP_ASYNC16(nb + 16384 + loff[i], Wg + boff[i] + kadd);
            }
            CP_COMMIT();
            CP_WAIT2();
        } else if (s + 1 < NS) {
            CP_WAIT1();
        } else {
            CP_WAIT0();
        }
        __syncthreads();

        const uint32_t aBase = sb + buf * 32768;
        const uint32_t bBase = aBase + 16384;
#pragma unroll
        for (int kk = 0; kk < 4; kk++) {
            uint32_t af[4][4];
#pragma unroll
            for (int mf = 0; mf < 4; mf++) {
                uint32_t addr = aBase + rowA[mf] * 128 +
                                (((kk * 2 + kcA) ^ (rowA[mf] & 7)) << 4);
                LDSM_X4(af[mf][0], af[mf][1], af[mf][2], af[mf][3], addr);
            }
            uint32_t bf[2][4];
#pragma unroll
            for (int nb2 = 0; nb2 < 2; nb2++) {
                uint32_t addr = bBase + rowB[nb2] * 128 +
                                (((kk * 2 + kcB) ^ (rowB[nb2] & 7)) << 4);
                LDSM_X4(bf[nb2][0], bf[nb2][1], bf[nb2][2], bf[nb2][3], addr);
            }
#pragma unroll
            for (int mf = 0; mf < 4; mf++)
#pragma unroll
                for (int nf = 0; nf < 4; nf++)
                    mma_fp16(acc[mf][nf], af[mf], &bf[nf >> 1][(nf & 1) * 2]);
        }
        __syncthreads();
        buf = (buf + 1) % 3;
    }

    // ---------------- epilogue ----------------
    if (MODE == 2) {
        float* stg = (float*)smem;  // 128 x 129 fp32 staging
#pragma unroll
        for (int mf = 0; mf < 4; mf++)
#pragma unroll
            for (int nf = 0; nf < 4; nf++)
#pragma unroll
                for (int half = 0; half < 2; half++) {
                    int rl = warp_m * 64 + mf * 16 + (lane >> 2) + half * 8;
                    int cl = warp_n * 32 + nf * 8 + (lane & 3) * 2;
                    stg[rl * 129 + cl] = fmaf(acc[mf][nf][half * 2 + 0], s_scale[cl], s_shift[cl]);
                    stg[rl * 129 + cl + 1] =
                        fmaf(acc[mf][nf][half * 2 + 1], s_scale[cl + 1], s_shift[cl + 1]);
                }
        __syncthreads();
        float* out = (float*)dstv;
#pragma unroll
        for (int cc = 0; cc < 16; cc++) {
            int c = wid * 16 + cc;
#pragma unroll
            for (int j = 0; j < 4; j++) {
                int i = lane + 32 * j;
                int r = r0 + i;
                int b = r / SPX;
                size_t o = ((size_t)(b * DIM + n0 + c)) * SPX + (r - b * SPX);
                out[o] = stg[i * 129 + c] + xres[o];
            }
        }
        return;
    }

    const int mw = r0 + warp_m * 64;
    const int nw = warp_n * 32;
    __half* dp_base = (__half*)dstv;
#pragma unroll
    for (int mf = 0; mf < 4; mf++) {
#pragma unroll
        for (int nf = 0; nf < 4; nf++) {
#pragma unroll
            for (int half = 0; half < 2; half++) {
                int grow = mw + mf * 16 + (lane >> 2) + half * 8;
                int lcol = nw + nf * 8 + (lane & 3) * 2;
                float v0 = fmaf(acc[mf][nf][half * 2 + 0], s_scale[lcol], s_shift[lcol]);
                float v1 = fmaf(acc[mf][nf][half * 2 + 1], s_scale[lcol + 1], s_shift[lcol + 1]);
                if (MODE == 1) {
                    v0 = 0.5f * v0 * (1.0f + erff(v0 * 0.70710678118654752f));
                    v1 = 0.5f * v1 * (1.0f + erff(v1 * 0.70710678118654752f));
                }
                __half2 hp;
                hp.x = __float2half_rn(v0);
                hp.y = __float2half_rn(v1);
                *(__half2*)(dp_base + (size_t)grow * DIM2 + n0 + lcol) = hp;
            }
        }
    }
}

// ---------------------------------------------------------------------------
extern "C" void kernel_launch(void* const* d_in, const int* in_sizes, int n_in,
                              void* d_out, int out_size) {
    const float* x   = (const float*)d_in[0];
    const float* w1  = (const float*)d_in[1];
    const float* b1  = (const float*)d_in[2];
    const float* g1  = (const float*)d_in[3];
    const float* be1 = (const float*)d_in[4];
    const float* m1  = (const float*)d_in[5];
    const float* v1  = (const float*)d_in[6];
    const float* wg  = (const float*)d_in[7];
    const float* bg  = (const float*)d_in[8];
    const float* gg  = (const float*)d_in[9];
    const float* beg = (const float*)d_in[10];
    const float* mg  = (const float*)d_in[11];
    const float* vg  = (const float*)d_in[12];
    const float* w2  = (const float*)d_in[13];
    const float* b2  = (const float*)d_in[14];
    const float* g2  = (const float*)d_in[15];
    const float* be2 = (const float*)d_in[16];
    const float* m2  = (const float*)d_in[17];
    const float* v2  = (const float*)d_in[18];

    __half *xTh, *cath, *gh, *w1h, *wgh, *w2h;
    float *sc1, *sh1, *scg, *shg, *sc2, *sh2;
    cudaGetSymbolAddress((void**)&xTh, g_xTh);
    cudaGetSymbolAddress((void**)&cath, g_cath);
    cudaGetSymbolAddress((void**)&gh, g_gh);
    cudaGetSymbolAddress((void**)&w1h, g_w1h);
    cudaGetSymbolAddress((void**)&wgh, g_wgh);
    cudaGetSymbolAddress((void**)&w2h, g_w2h);
    cudaGetSymbolAddress((void**)&sc1, g_sc1);
    cudaGetSymbolAddress((void**)&sh1, g_sh1);
    cudaGetSymbolAddress((void**)&scg, g_scg);
    cudaGetSymbolAddress((void**)&shg, g_shg);
    cudaGetSymbolAddress((void**)&sc2, g_sc2);
    cudaGetSymbolAddress((void**)&sh2, g_sh2);

    cudaFuncSetAttribute(fp16_gemm<0>, cudaFuncAttributeMaxDynamicSharedMemorySize, GSMEM);
    cudaFuncSetAttribute(fp16_gemm<1>, cudaFuncAttributeMaxDynamicSharedMemorySize, GSMEM);
    cudaFuncSetAttribute(fp16_gemm<2>, cudaFuncAttributeMaxDynamicSharedMemorySize, GSMEM);

    prep_pack<<<1793, 256>>>(w1, wg, w2, b1, g1, be1, m1, v1,
                             bg, gg, beg, mg, vg, b2, g2, be2, m2, v2);
    transpose_in_pack<<<dim3(98, 8, 8), 256>>>(x);

    // fc1: cat[:, 0:256] = fp16(BN(x @ w1^T))
    fp16_gemm<0><<<dim3(196, 2), 256, GSMEM>>>(xTh, w1h, cath, nullptr, sc1, sh1, DIM);
    // MRConv4d -> cat[:, 256:512]
    colmin_kernel<<<dim3(56, 8), 256>>>();
    row_combine_kernel<<<dim3(56, 8), 256>>>();
    // g = fp16(GELU(BN(cat @ wg^T)))
    fp16_gemm<1><<<dim3(196, 4), 256, GSMEM>>>(cath, wgh, gh, nullptr, scg, shg, DIM2);
    // out[B,256,S] = BN(g @ w2^T)^T + x  (fused transpose + residual)
    fp16_gemm<2><<<dim3(196, 2), 256, GSMEM>>>(gh, w2h, d_out, x, sc2, sh2, DIM2);
}

// round 9
// speedup vs baseline: 1.6843x; 1.0923x over previous
#include <cuda_runtime.h>
#include <cuda_fp16.h>
#include <cstdint>

#define SPX 3136      // 56*56
#define BATCH 8
#define DIM 256
#define DIM2 512
#define ROWS_TOT (BATCH * SPX)   // 25088 = 196 * 128

// ---------------- scratch (static __device__, allocation-free) ----------------
__device__ __half g_xTh[(size_t)ROWS_TOT * DIM];     // fp16(x^T) [B*S, 256]
__device__ __half g_cath[(size_t)ROWS_TOT * DIM2];   // [B*S, 512] = [h | xj]
__device__ __half g_gh[(size_t)ROWS_TOT * DIM2];     // gelu out [B*S, 512]
__device__ __half g_w1h[(size_t)DIM * DIM];          // fp16(w1) [256,256]
__device__ __half g_wgh[(size_t)DIM2 * DIM2];        // fp16(wg) [512,512]
__device__ __half g_w2h[(size_t)DIM * DIM2];         // fp16(w2) [256,512]
// column-min partials: [B][56 x][2 y-half][2 parity][256 c]
__device__ float g_cm1[(size_t)BATCH * 56 * 2 * 2 * DIM];
__device__ float g_cm2[(size_t)BATCH * 56 * 2 * 2 * DIM];
__device__ float g_sc1[DIM], g_sh1[DIM];
__device__ float g_scg[DIM2], g_shg[DIM2];
__device__ float g_sc2[DIM], g_sh2[DIM];

// ---------------- PTX helpers (sm_80-generic only) ----------------
__device__ __forceinline__ uint32_t smem_u32(const void* p) {
    uint32_t a;
    asm("{ .reg .u64 t; cvta.to.shared.u64 t, %1; cvt.u32.u64 %0, t; }" : "=r"(a) : "l"(p));
    return a;
}
#define CP_ASYNC16(sm, gm) \
    asm volatile("cp.async.cg.shared.global [%0], [%1], 16;" :: "r"(sm), "l"(gm) : "memory")
#define CP_COMMIT() asm volatile("cp.async.commit_group;" ::: "memory")
#define CP_WAIT1() asm volatile("cp.async.wait_group 1;" ::: "memory")
#define CP_WAIT0() asm volatile("cp.async.wait_group 0;" ::: "memory")
#define LDSM_X4(r0, r1, r2, r3, addr)                                        \
    asm volatile("ldmatrix.sync.aligned.m8n8.x4.shared.b16 {%0,%1,%2,%3}, [%4];" \
                 : "=r"(r0), "=r"(r1), "=r"(r2), "=r"(r3) : "r"(addr))

__device__ __forceinline__ void mma_fp16(float* d, const uint32_t* a, const uint32_t* b) {
    asm volatile(
        "mma.sync.aligned.m16n8k16.row.col.f32.f16.f16.f32 "
        "{%0,%1,%2,%3}, {%4,%5,%6,%7}, {%8,%9}, {%0,%1,%2,%3};"
        : "+f"(d[0]), "+f"(d[1]), "+f"(d[2]), "+f"(d[3])
        : "r"(a[0]), "r"(a[1]), "r"(a[2]), "r"(a[3]), "r"(b[0]), "r"(b[1]));
}

// two-smallest merge (exact)
__device__ __forceinline__ void ts_merge(float a1, float a2, float b1, float b2,
                                         float& r1, float& r2) {
    r1 = fminf(a1, b1);
    r2 = fminf(fmaxf(a1, b1), fminf(a2, b2));
}

// ---------------- fused prep + vectorized weight packing ----------------
// blocks [0,448): float4->2x half2 convert of w1|wg|w2 (clean block boundaries)
// block 448: fold conv bias + BN into scale/shift
__global__ void prep_pack(const float* __restrict__ w1, const float* __restrict__ wg,
                          const float* __restrict__ w2,
                          const float* __restrict__ b1, const float* __restrict__ g1,
                          const float* __restrict__ be1, const float* __restrict__ m1,
                          const float* __restrict__ v1,
                          const float* __restrict__ bg, const float* __restrict__ gg,
                          const float* __restrict__ beg, const float* __restrict__ mg,
                          const float* __restrict__ vg,
                          const float* __restrict__ b2, const float* __restrict__ g2,
                          const float* __restrict__ be2, const float* __restrict__ m2,
                          const float* __restrict__ v2) {
    int blk = blockIdx.x;
    if (blk < 448) {
        int idx = blk * 256 + threadIdx.x;  // float4 index
        const float4* src;
        __half* dst;
        if (blk < 64) { src = (const float4*)w1; dst = g_w1h; }
        else if (blk < 320) { src = (const float4*)wg; dst = g_wgh; idx -= 16384; }
        else { src = (const float4*)w2; dst = g_w2h; idx -= 81920; }
        float4 f = src[idx];
        __half2 h0 = __floats2half2_rn(f.x, f.y);
        __half2 h1 = __floats2half2_rn(f.z, f.w);
        *(__half2*)(dst + (size_t)idx * 4) = h0;
        *(__half2*)(dst + (size_t)idx * 4 + 2) = h1;
        return;
    }
    int i = threadIdx.x;
    {
        float s = g1[i] / sqrtf(v1[i] + 1e-5f);
        g_sc1[i] = s; g_sh1[i] = (b1[i] - m1[i]) * s + be1[i];
        float s2 = g2[i] / sqrtf(v2[i] + 1e-5f);
        g_sc2[i] = s2; g_sh2[i] = (b2[i] - m2[i]) * s2 + be2[i];
    }
#pragma unroll
    for (int r = 0; r < 2; r++) {
        int j = i + r * 256;
        float sg = gg[j] / sqrtf(vg[j] + 1e-5f);
        g_scg[j] = sg; g_shg[j] = (bg[j] - mg[j]) * sg + beg[j];
    }
}

// ---------------- transpose x [B,256,S] -> fp16 [B*S, 256] ----------------
__global__ void __launch_bounds__(256) transpose_in_pack(const float* __restrict__ x) {
    __shared__ float t[32][33];
    int tx = threadIdx.x & 31, ty = threadIdx.x >> 5;
    int s0 = blockIdx.x * 32, c0 = blockIdx.y * 32, b = blockIdx.z;
    const float* xp = x + ((size_t)b * DIM + c0) * SPX + s0;
    for (int i = ty; i < 32; i += 8) t[i][tx] = xp[(size_t)i * SPX + tx];
    __syncthreads();
    __half* op = g_xTh + ((size_t)(b * SPX + s0)) * DIM + c0;
    for (int i = ty; i < 32; i += 8)
        op[(size_t)i * DIM + tx] = __float2half_rn(t[tx][i]);
}

// ---------------- MRConv4d: column pass split over y-halves ----------------
// grid (56, 8, 2): z = y-half; each block scans 28 rows (14 per parity).
__global__ void __launch_bounds__(256) colmin_kernel() {
    int x = blockIdx.x, b = blockIdx.y, h = blockIdx.z, c = threadIdx.x;
    const __half* base = g_cath + ((size_t)(b * SPX + h * 28 * 56 + x)) * DIM2 + c;
    float a1e = 1e30f, a2e = 1e30f, a1o = 1e30f, a2o = 1e30f;
    for (int i = 0; i < 28; i += 2) {
        float v = __half2float(base[(size_t)(i * 56) * DIM2]);
        if (v < a1e) { a2e = a1e; a1e = v; } else if (v < a2e) a2e = v;
        float w = __half2float(base[(size_t)((i + 1) * 56) * DIM2]);
        if (w < a1o) { a2o = a1o; a1o = w; } else if (w < a2o) a2o = w;
    }
    // [B][56][2 half][2 parity][256]
    size_t o = (((size_t)(b * 56 + x) * 2 + h) * 2) * DIM + c;
    g_cm1[o] = a1e; g_cm2[o] = a2e;
    g_cm1[o + DIM] = a1o; g_cm2[o + DIM] = a2o;
}

// ---------------- MRConv4d: row pass + combine -> xj ----------------
__global__ void __launch_bounds__(256) row_combine_kernel() {
    int y = blockIdx.x, b = blockIdx.y, c = threadIdx.x;
    const __half* base = g_cath + ((size_t)(b * SPX + y * 56)) * DIM2 + c;
    float r1e = 1e30f, r2e = 1e30f, r1o = 1e30f, r2o = 1e30f;
    float hv[56];
    for (int x = 0; x < 56; x += 2) {
        float v = __half2float(base[(size_t)x * DIM2]);
        hv[x] = v;
        if (v < r1e) { r2e = r1e; r1e = v; } else if (v < r2e) r2e = v;
        float w = __half2float(base[(size_t)(x + 1) * DIM2]);
        hv[x + 1] = w;
        if (w < r1o) { r2o = r1o; r1o = w; } else if (w < r2o) r2o = w;
    }
    int py = y & 1;
    __half* ob = g_cath + ((size_t)(b * SPX + y * 56)) * DIM2 + DIM + c;
    // cm base for (b, x=0, half, py): offsets below
    const size_t cmb = (((size_t)(b * 56) * 2 + 0) * 2 + py) * DIM + c;
    for (int x = 0; x < 56; x++) {
        float v = hv[x];
        size_t o0 = cmb + (size_t)x * 4 * DIM;          // half 0
        size_t o1 = o0 + 2 * DIM;                        // half 1
        float c1, c2;
        ts_merge(g_cm1[o0], g_cm2[o0], g_cm1[o1], g_cm2[o1], c1, c2);
        float ec = (v == c1) ? c2 : c1;
        float r1 = (x & 1) ? r1o : r1e, r2 = (x & 1) ? r2o : r2e;
        float er = (v == r1) ? r2 : r1;
        ob[(size_t)x * DIM2] = __float2half_rn(fmaxf(0.0f, v - fminf(ec, er)));
    }
}

// ---------------- fp16 mma.sync GEMM (R5 shape, compile-time K, full unroll) ----------------
// CTA 128x128, 8 warps (2m x 4n) of 64x32, BK=64, 256 threads, 2 CTAs/SM, 2-stage.
// MODE 0: BN -> fp16, row stride 512 (fc1)
// MODE 1: BN + exact GELU -> fp16, row stride 512 (gemm2)
// MODE 2: BN + residual -> transposed fp32 out[B,256,S] via 128x129 staged transpose
#define GSMEM 66560
template <int MODE, int K>
__global__ void __launch_bounds__(256, 2)
fp16_gemm(const __half* __restrict__ Ag, const __half* __restrict__ Wg,
          void* __restrict__ dstv, const float* __restrict__ xres,
          const float* __restrict__ scale, const float* __restrict__ shift) {
    extern __shared__ __align__(1024) char smem[];
    __shared__ float s_scale[128], s_shift[128];
    const int tid = threadIdx.x, lane = tid & 31, wid = tid >> 5;
    const int warp_m = wid >> 2, warp_n = wid & 3;
    const int r0 = blockIdx.x * 128, n0 = blockIdx.y * 128;
    const uint32_t sb = smem_u32(smem);
    if (tid < 128) { s_scale[tid] = scale[n0 + tid]; s_shift[tid] = shift[n0 + tid]; }

    uint32_t loff[4];
    size_t aoff[4], boff[4];
#pragma unroll
    for (int i = 0; i < 4; i++) {
        int idx = tid + i * 256;
        int row = idx >> 3, c = idx & 7;
        loff[i] = row * 128 + ((c ^ (row & 7)) << 4);
        aoff[i] = (size_t)(r0 + row) * K + c * 8;
        boff[i] = (size_t)(n0 + row) * K + c * 8;
    }

    const int rowA[4] = {warp_m * 64 + 0 * 16 + (lane & 7) + ((lane >> 3) & 1) * 8,
                         warp_m * 64 + 1 * 16 + (lane & 7) + ((lane >> 3) & 1) * 8,
                         warp_m * 64 + 2 * 16 + (lane & 7) + ((lane >> 3) & 1) * 8,
                         warp_m * 64 + 3 * 16 + (lane & 7) + ((lane >> 3) & 1) * 8};
    const int kcA = lane >> 4;
    const int rowB[2] = {warp_n * 32 + 0 * 16 + (lane & 7) + ((lane >> 4) & 1) * 8,
                         warp_n * 32 + 1 * 16 + (lane & 7) + ((lane >> 4) & 1) * 8};
    const int kcB = (lane >> 3) & 1;

    float acc[4][4][4];
#pragma unroll
    for (int a = 0; a < 4; a++)
#pragma unroll
        for (int b = 0; b < 4; b++)
#pragma unroll
            for (int i = 0; i < 4; i++) acc[a][b][i] = 0.0f;

    constexpr int NS = K >> 6;

    // prologue: stage 0 -> buf 0
#pragma unroll
    for (int i = 0; i < 4; i++) {
        CP_ASYNC16(sb + loff[i], Ag + aoff[i]);
        CP_ASYNC16(sb + 16384 + loff[i], Wg + boff[i]);
    }
    CP_COMMIT();

#pragma unroll
    for (int s = 0; s < NS; s++) {
        const uint32_t aBase = sb + (s & 1) * 32768;
        const uint32_t bBase = aBase + 16384;
        if (s + 1 < NS) {
            const uint32_t nb = sb + ((s + 1) & 1) * 32768;
            const size_t kadd = (size_t)(s + 1) * 64;
#pragma unroll
            for (int i = 0; i < 4; i++) {
                CP_ASYNC16(nb + loff[i], Ag + aoff[i] + kadd);
                CP_ASYNC16(nb + 16384 + loff[i], Wg + boff[i] + kadd);
            }
            CP_COMMIT();
            CP_WAIT1();
        } else {
            CP_WAIT0();
        }
        __syncthreads();

#pragma unroll
        for (int kk = 0; kk < 4; kk++) {
            uint32_t af[4][4];
#pragma unroll
            for (int mf = 0; mf < 4; mf++) {
                uint32_t addr = aBase + rowA[mf] * 128 +
                                (((kk * 2 + kcA) ^ (rowA[mf] & 7)) << 4);
                LDSM_X4(af[mf][0], af[mf][1], af[mf][2], af[mf][3], addr);
            }
            uint32_t bf[2][4];
#pragma unroll
            for (int nb2 = 0; nb2 < 2; nb2++) {
                uint32_t addr = bBase + rowB[nb2] * 128 +
                                (((kk * 2 + kcB) ^ (rowB[nb2] & 7)) << 4);
                LDSM_X4(bf[nb2][0], bf[nb2][1], bf[nb2][2], bf[nb2][3], addr);
            }
#pragma unroll
            for (int mf = 0; mf < 4; mf++)
#pragma unroll
                for (int nf = 0; nf < 4; nf++)
                    mma_fp16(acc[mf][nf], af[mf], &bf[nf >> 1][(nf & 1) * 2]);
        }
        __syncthreads();
    }

    // ---------------- epilogue ----------------
    if (MODE == 2) {
        float* stg = (float*)smem;  // 128 x 129 fp32 staging
#pragma unroll
        for (int mf = 0; mf < 4; mf++)
#pragma unroll
            for (int nf = 0; nf < 4; nf++)
#pragma unroll
                for (int half = 0; half < 2; half++) {
                    int rl = warp_m * 64 + mf * 16 + (lane >> 2) + half * 8;
                    int cl = warp_n * 32 + nf * 8 + (lane & 3) * 2;
                    stg[rl * 129 + cl] = fmaf(acc[mf][nf][half * 2 + 0], s_scale[cl], s_shift[cl]);
                    stg[rl * 129 + cl + 1] =
                        fmaf(acc[mf][nf][half * 2 + 1], s_scale[cl + 1], s_shift[cl + 1]);
                }
        __syncthreads();
        float* out = (float*)dstv;
#pragma unroll
        for (int cc = 0; cc < 16; cc++) {
            int c = wid * 16 + cc;
#pragma unroll
            for (int j = 0; j < 4; j++) {
                int i = lane + 32 * j;
                int r = r0 + i;
                int b = r / SPX;
                size_t o = ((size_t)(b * DIM + n0 + c)) * SPX + (r - b * SPX);
                out[o] = stg[i * 129 + c] + xres[o];
            }
        }
        return;
    }

    const int mw = r0 + warp_m * 64;
    const int nw = warp_n * 32;
    __half* dp_base = (__half*)dstv;
#pragma unroll
    for (int mf = 0; mf < 4; mf++) {
#pragma unroll
        for (int nf = 0; nf < 4; nf++) {
#pragma unroll
            for (int half = 0; half < 2; half++) {
                int grow = mw + mf * 16 + (lane >> 2) + half * 8;
                int lcol = nw + nf * 8 + (lane & 3) * 2;
                float v0 = fmaf(acc[mf][nf][half * 2 + 0], s_scale[lcol], s_shift[lcol]);
                float v1 = fmaf(acc[mf][nf][half * 2 + 1], s_scale[lcol + 1], s_shift[lcol + 1]);
                if (MODE == 1) {
                    v0 = 0.5f * v0 * (1.0f + erff(v0 * 0.70710678118654752f));
                    v1 = 0.5f * v1 * (1.0f + erff(v1 * 0.70710678118654752f));
                }
                __half2 hp;
                hp.x = __float2half_rn(v0);
                hp.y = __float2half_rn(v1);
                *(__half2*)(dp_base + (size_t)grow * DIM2 + n0 + lcol) = hp;
            }
        }
    }
}

// ---------------------------------------------------------------------------
extern "C" void kernel_launch(void* const* d_in, const int* in_sizes, int n_in,
                              void* d_out, int out_size) {
    const float* x   = (const float*)d_in[0];
    const float* w1  = (const float*)d_in[1];
    const float* b1  = (const float*)d_in[2];
    const float* g1  = (const float*)d_in[3];
    const float* be1 = (const float*)d_in[4];
    const float* m1  = (const float*)d_in[5];
    const float* v1  = (const float*)d_in[6];
    const float* wg  = (const float*)d_in[7];
    const float* bg  = (const float*)d_in[8];
    const float* gg  = (const float*)d_in[9];
    const float* beg = (const float*)d_in[10];
    const float* mg  = (const float*)d_in[11];
    const float* vg  = (const float*)d_in[12];
    const float* w2  = (const float*)d_in[13];
    const float* b2  = (const float*)d_in[14];
    const float* g2  = (const float*)d_in[15];
    const float* be2 = (const float*)d_in[16];
    const float* m2  = (const float*)d_in[17];
    const float* v2  = (const float*)d_in[18];

    __half *xTh, *cath, *gh, *w1h, *wgh, *w2h;
    float *sc1, *sh1, *scg, *shg, *sc2, *sh2;
    cudaGetSymbolAddress((void**)&xTh, g_xTh);
    cudaGetSymbolAddress((void**)&cath, g_cath);
    cudaGetSymbolAddress((void**)&gh, g_gh);
    cudaGetSymbolAddress((void**)&w1h, g_w1h);
    cudaGetSymbolAddress((void**)&wgh, g_wgh);
    cudaGetSymbolAddress((void**)&w2h, g_w2h);
    cudaGetSymbolAddress((void**)&sc1, g_sc1);
    cudaGetSymbolAddress((void**)&sh1, g_sh1);
    cudaGetSymbolAddress((void**)&scg, g_scg);
    cudaGetSymbolAddress((void**)&shg, g_shg);
    cudaGetSymbolAddress((void**)&sc2, g_sc2);
    cudaGetSymbolAddress((void**)&sh2, g_sh2);

    cudaFuncSetAttribute(fp16_gemm<0, 256>, cudaFuncAttributeMaxDynamicSharedMemorySize, GSMEM);
    cudaFuncSetAttribute(fp16_gemm<1, 512>, cudaFuncAttributeMaxDynamicSharedMemorySize, GSMEM);
    cudaFuncSetAttribute(fp16_gemm<2, 512>, cudaFuncAttributeMaxDynamicSharedMemorySize, GSMEM);

    prep_pack<<<449, 256>>>(w1, wg, w2, b1, g1, be1, m1, v1,
                            bg, gg, beg, mg, vg, b2, g2, be2, m2, v2);
    transpose_in_pack<<<dim3(98, 8, 8), 256>>>(x);

    // fc1: cat[:, 0:256] = fp16(BN(x @ w1^T))
    fp16_gemm<0, 256><<<dim3(196, 2), 256, GSMEM>>>(xTh, w1h, cath, nullptr, sc1, sh1);
    // MRConv4d -> cat[:, 256:512]
    colmin_kernel<<<dim3(56, 8, 2), 256>>>();
    row_combine_kernel<<<dim3(56, 8), 256>>>();
    // g = fp16(GELU(BN(cat @ wg^T)))
    fp16_gemm<1, 512><<<dim3(196, 4), 256, GSMEM>>>(cath, wgh, gh, nullptr, scg, shg);
    // out[B,256,S] = BN(g @ w2^T)^T + x  (fused transpose + residual)
    fp16_gemm<2, 512><<<dim3(196, 2), 256, GSMEM>>>(gh, w2h, d_out, x, sc2, sh2);
}

// round 10
// speedup vs baseline: 1.7052x; 1.0124x over previous
#include <cuda_runtime.h>
#include <cuda_fp16.h>
#include <cstdint>

#define SPX 3136      // 56*56
#define BATCH 8
#define DIM 256
#define DIM2 512
#define ROWS_TOT (BATCH * SPX)   // 25088 = 196 * 128

// ---------------- scratch (static __device__, allocation-free) ----------------
__device__ __half g_xTh[(size_t)ROWS_TOT * DIM];     // fp16(x^T) [B*S, 256]
__device__ __half g_cath[(size_t)ROWS_TOT * DIM2];   // [B*S, 512] = [h | xj]; reused as fp32
                                                     // split-K partial scratch for fc2
__device__ __half g_gh[(size_t)ROWS_TOT * DIM2];     // gelu out [B*S, 512]
__device__ __half g_w1h[(size_t)DIM * DIM];          // fp16(w1) [256,256]
__device__ __half g_wgh[(size_t)DIM2 * DIM2];        // fp16(wg) [512,512]
__device__ __half g_w2h[(size_t)DIM * DIM2];         // fp16(w2) [256,512]
// column-min partials: [B][56 x][2 y-half][2 parity][256 c]
__device__ float g_cm1[(size_t)BATCH * 56 * 2 * 2 * DIM];
__device__ float g_cm2[(size_t)BATCH * 56 * 2 * 2 * DIM];
// row-min partials: [B][56 y][2 x-half][2 parity][256 c]
__device__ float g_rm1[(size_t)BATCH * 56 * 2 * 2 * DIM];
__device__ float g_rm2[(size_t)BATCH * 56 * 2 * 2 * DIM];
__device__ int g_flags[392];                          // fc2 split-K tile flags
__device__ float g_sc1[DIM], g_sh1[DIM];
__device__ float g_scg[DIM2], g_shg[DIM2];
__device__ float g_sc2[DIM], g_sh2[DIM];

// ---------------- PTX helpers (sm_80-generic only) ----------------
__device__ __forceinline__ uint32_t smem_u32(const void* p) {
    uint32_t a;
    asm("{ .reg .u64 t; cvta.to.shared.u64 t, %1; cvt.u32.u64 %0, t; }" : "=r"(a) : "l"(p));
    return a;
}
#define CP_ASYNC16(sm, gm) \
    asm volatile("cp.async.cg.shared.global [%0], [%1], 16;" :: "r"(sm), "l"(gm) : "memory")
#define CP_COMMIT() asm volatile("cp.async.commit_group;" ::: "memory")
#define CP_WAIT1() asm volatile("cp.async.wait_group 1;" ::: "memory")
#define CP_WAIT0() asm volatile("cp.async.wait_group 0;" ::: "memory")
#define LDSM_X4(r0, r1, r2, r3, addr)                                        \
    asm volatile("ldmatrix.sync.aligned.m8n8.x4.shared.b16 {%0,%1,%2,%3}, [%4];" \
                 : "=r"(r0), "=r"(r1), "=r"(r2), "=r"(r3) : "r"(addr))

__device__ __forceinline__ void mma_fp16(float* d, const uint32_t* a, const uint32_t* b) {
    asm volatile(
        "mma.sync.aligned.m16n8k16.row.col.f32.f16.f16.f32 "
        "{%0,%1,%2,%3}, {%4,%5,%6,%7}, {%8,%9}, {%0,%1,%2,%3};"
        : "+f"(d[0]), "+f"(d[1]), "+f"(d[2]), "+f"(d[3])
        : "r"(a[0]), "r"(a[1]), "r"(a[2]), "r"(a[3]), "r"(b[0]), "r"(b[1]));
}

// two-smallest merge (exact)
__device__ __forceinline__ void ts_merge(float a1, float a2, float b1, float b2,
                                         float& r1, float& r2) {
    r1 = fminf(a1, b1);
    r2 = fminf(fmaxf(a1, b1), fminf(a2, b2));
}

// ---------------- fused transpose_in + prep + weight packing + flag reset ----------------
// blocks [0, 6272): transpose x [B,256,S] -> fp16 [B*S, 256]
// blocks [6272, 6720): float4 -> half2x2 weight convert (w1|wg|w2)
// block 6720: BN fold + flag zeroing
__global__ void __launch_bounds__(256) fused_prep(const float* __restrict__ x,
                          const float* __restrict__ w1, const float* __restrict__ wg,
                          const float* __restrict__ w2,
                          const float* __restrict__ b1, const float* __restrict__ g1,
                          const float* __restrict__ be1, const float* __restrict__ m1,
                          const float* __restrict__ v1,
                          const float* __restrict__ bg, const float* __restrict__ gg,
                          const float* __restrict__ beg, const float* __restrict__ mg,
                          const float* __restrict__ vg,
                          const float* __restrict__ b2, const float* __restrict__ g2,
                          const float* __restrict__ be2, const float* __restrict__ m2,
                          const float* __restrict__ v2) {
    int blk = blockIdx.x;
    if (blk < 6272) {
        __shared__ float t[32][33];
        int tx = threadIdx.x & 31, ty = threadIdx.x >> 5;
        int s0 = (blk % 98) * 32, c0 = ((blk / 98) & 7) * 32, b = blk / 784;
        const float* xp = x + ((size_t)b * DIM + c0) * SPX + s0;
        for (int i = ty; i < 32; i += 8) t[i][tx] = xp[(size_t)i * SPX + tx];
        __syncthreads();
        __half* op = g_xTh + ((size_t)(b * SPX + s0)) * DIM + c0;
        for (int i = ty; i < 32; i += 8)
            op[(size_t)i * DIM + tx] = __float2half_rn(t[tx][i]);
        return;
    }
    if (blk < 6720) {
        int pb = blk - 6272;
        int idx = pb * 256 + threadIdx.x;  // float4 index
        const float4* src;
        __half* dst;
        if (pb < 64) { src = (const float4*)w1; dst = g_w1h; }
        else if (pb < 320) { src = (const float4*)wg; dst = g_wgh; idx -= 16384; }
        else { src = (const float4*)w2; dst = g_w2h; idx -= 81920; }
        float4 f = src[idx];
        *(__half2*)(dst + (size_t)idx * 4) = __floats2half2_rn(f.x, f.y);
        *(__half2*)(dst + (size_t)idx * 4 + 2) = __floats2half2_rn(f.z, f.w);
        return;
    }
    int i = threadIdx.x;
    {
        float s = g1[i] / sqrtf(v1[i] + 1e-5f);
        g_sc1[i] = s; g_sh1[i] = (b1[i] - m1[i]) * s + be1[i];
        float s2 = g2[i] / sqrtf(v2[i] + 1e-5f);
        g_sc2[i] = s2; g_sh2[i] = (b2[i] - m2[i]) * s2 + be2[i];
    }
#pragma unroll
    for (int r = 0; r < 2; r++) {
        int j = i + r * 256;
        float sg = gg[j] / sqrtf(vg[j] + 1e-5f);
        g_scg[j] = sg; g_shg[j] = (bg[j] - mg[j]) * sg + beg[j];
    }
    g_flags[i] = 0;
    if (i + 256 < 392) g_flags[i + 256] = 0;
}

// ---------------- MRConv4d pass 1: col + row partial two-smallest ----------------
// grid (56, 8, 4): z<2 -> column pass (x = bx, y-half = z)
//                  z>=2 -> row pass (y = bx, x-half = z-2)
__global__ void __launch_bounds__(256) minpass_kernel() {
    int b = blockIdx.y, c = threadIdx.x;
    float a1e = 1e30f, a2e = 1e30f, a1o = 1e30f, a2o = 1e30f;
    if (blockIdx.z < 2) {
        int x = blockIdx.x, h = blockIdx.z;
        const __half* base = g_cath + ((size_t)(b * SPX + h * 28 * 56 + x)) * DIM2 + c;
        for (int i = 0; i < 28; i += 2) {
            float v = __half2float(base[(size_t)(i * 56) * DIM2]);
            if (v < a1e) { a2e = a1e; a1e = v; } else if (v < a2e) a2e = v;
            float w = __half2float(base[(size_t)((i + 1) * 56) * DIM2]);
            if (w < a1o) { a2o = a1o; a1o = w; } else if (w < a2o) a2o = w;
        }
        size_t o = (((size_t)(b * 56 + x) * 2 + h) * 2) * DIM + c;
        g_cm1[o] = a1e; g_cm2[o] = a2e;
        g_cm1[o + DIM] = a1o; g_cm2[o + DIM] = a2o;
    } else {
        int y = blockIdx.x, h = blockIdx.z - 2;
        const __half* base = g_cath + ((size_t)(b * SPX + y * 56 + h * 28)) * DIM2 + c;
        for (int i = 0; i < 28; i += 2) {
            float v = __half2float(base[(size_t)i * DIM2]);
            if (v < a1e) { a2e = a1e; a1e = v; } else if (v < a2e) a2e = v;
            float w = __half2float(base[(size_t)(i + 1) * DIM2]);
            if (w < a1o) { a2o = a1o; a1o = w; } else if (w < a2o) a2o = w;
        }
        size_t o = (((size_t)(b * 56 + y) * 2 + h) * 2) * DIM + c;
        g_rm1[o] = a1e; g_rm2[o] = a2e;
        g_rm1[o + DIM] = a1o; g_rm2[o + DIM] = a2o;
    }
}

// ---------------- MRConv4d pass 2: combine -> xj ----------------
// grid (56, 8, 2): y = bx, b = by, x-half = bz; each block does 28 x's.
__global__ void __launch_bounds__(256) combine_kernel() {
    int y = blockIdx.x, b = blockIdx.y, xh = blockIdx.z, c = threadIdx.x;
    // merged row mins for this (b, y): parity 0 and 1
    float r1[2], r2[2];
    {
        size_t o0 = (((size_t)(b * 56 + y) * 2 + 0) * 2) * DIM + c;
        size_t o1 = o0 + 2 * DIM;
#pragma unroll
        for (int p = 0; p < 2; p++)
            ts_merge(g_rm1[o0 + p * DIM], g_rm2[o0 + p * DIM],
                     g_rm1[o1 + p * DIM], g_rm2[o1 + p * DIM], r1[p], r2[p]);
    }
    int py = y & 1;
    const __half* hb = g_cath + ((size_t)(b * SPX + y * 56 + xh * 28)) * DIM2 + c;
    __half* ob = g_cath + ((size_t)(b * SPX + y * 56 + xh * 28)) * DIM2 + DIM + c;
    const size_t cmb = (((size_t)(b * 56 + xh * 28) * 2) * 2 + py) * DIM + c;
    for (int i = 0; i < 28; i++) {
        float v = __half2float(hb[(size_t)i * DIM2]);
        size_t o0 = cmb + (size_t)i * 4 * DIM;  // y-half 0
        size_t o1 = o0 + 2 * DIM;               // y-half 1
        float c1, c2;
        ts_merge(g_cm1[o0], g_cm2[o0], g_cm1[o1], g_cm2[o1], c1, c2);
        float ec = (v == c1) ? c2 : c1;
        int p = i & 1;  // xh*28 even -> global x parity = i&1
        float er = (v == r1[p]) ? r2[p] : r1[p];
        ob[(size_t)i * DIM2] = __float2half_rn(fmaxf(0.0f, v - fminf(ec, er)));
    }
}

// ---------------- fp16 mma.sync GEMM ----------------
// CTA 128x128, 8 warps (2m x 4n) of 64x32, BK=64, 256 threads, 2 CTAs/SM, 2-stage.
// KSTRIDE = memory row stride of A/W; KLEN = K extent this CTA reduces.
// MODE 0: BN -> fp16, row stride 512 (fc1)
// MODE 1: BN + exact GELU -> fp16, row stride 512 (gemm2)
// MODE 2: split-K fc2. blockIdx.z = k-half. half 0: raw fp32 partial + flag.
//         half 1: wait flag, add partial, BN + residual + transposed fp32 store.
#define GSMEM 66560
template <int MODE, int KSTRIDE, int KLEN>
__global__ void __launch_bounds__(256, 2)
fp16_gemm(const __half* __restrict__ Ag, const __half* __restrict__ Wg,
          void* __restrict__ dstv, const float* __restrict__ xres,
          float* __restrict__ partial, int* __restrict__ flags,
          const float* __restrict__ scale, const float* __restrict__ shift) {
    extern __shared__ __align__(1024) char smem[];
    __shared__ float s_scale[128], s_shift[128];
    const int tid = threadIdx.x, lane = tid & 31, wid = tid >> 5;
    const int warp_m = wid >> 2, warp_n = wid & 3;
    const int r0 = blockIdx.x * 128, n0 = blockIdx.y * 128;
    const int koff = (MODE == 2) ? (int)blockIdx.z * KLEN : 0;
    const uint32_t sb = smem_u32(smem);
    if (tid < 128) { s_scale[tid] = scale[n0 + tid]; s_shift[tid] = shift[n0 + tid]; }

    uint32_t loff[4];
    size_t aoff[4], boff[4];
#pragma unroll
    for (int i = 0; i < 4; i++) {
        int idx = tid + i * 256;
        int row = idx >> 3, c = idx & 7;
        loff[i] = row * 128 + ((c ^ (row & 7)) << 4);
        aoff[i] = (size_t)(r0 + row) * KSTRIDE + koff + c * 8;
        boff[i] = (size_t)(n0 + row) * KSTRIDE + koff + c * 8;
    }

    const int rowA[4] = {warp_m * 64 + 0 * 16 + (lane & 7) + ((lane >> 3) & 1) * 8,
                         warp_m * 64 + 1 * 16 + (lane & 7) + ((lane >> 3) & 1) * 8,
                         warp_m * 64 + 2 * 16 + (lane & 7) + ((lane >> 3) & 1) * 8,
                         warp_m * 64 + 3 * 16 + (lane & 7) + ((lane >> 3) & 1) * 8};
    const int kcA = lane >> 4;
    const int rowB[2] = {warp_n * 32 + 0 * 16 + (lane & 7) + ((lane >> 4) & 1) * 8,
                         warp_n * 32 + 1 * 16 + (lane & 7) + ((lane >> 4) & 1) * 8};
    const int kcB = (lane >> 3) & 1;

    float acc[4][4][4];
#pragma unroll
    for (int a = 0; a < 4; a++)
#pragma unroll
        for (int b = 0; b < 4; b++)
#pragma unroll
            for (int i = 0; i < 4; i++) acc[a][b][i] = 0.0f;

    constexpr int NS = KLEN >> 6;

    // prologue: stage 0 -> buf 0
#pragma unroll
    for (int i = 0; i < 4; i++) {
        CP_ASYNC16(sb + loff[i], Ag + aoff[i]);
        CP_ASYNC16(sb + 16384 + loff[i], Wg + boff[i]);
    }
    CP_COMMIT();

#pragma unroll
    for (int s = 0; s < NS; s++) {
        const uint32_t aBase = sb + (s & 1) * 32768;
        const uint32_t bBase = aBase + 16384;
        if (s + 1 < NS) {
            const uint32_t nb = sb + ((s + 1) & 1) * 32768;
            const size_t kadd = (size_t)(s + 1) * 64;
#pragma unroll
            for (int i = 0; i < 4; i++) {
                CP_ASYNC16(nb + loff[i], Ag + aoff[i] + kadd);
                CP_ASYNC16(nb + 16384 + loff[i], Wg + boff[i] + kadd);
            }
            CP_COMMIT();
            CP_WAIT1();
        } else {
            CP_WAIT0();
        }
        __syncthreads();

#pragma unroll
        for (int kk = 0; kk < 4; kk++) {
            uint32_t af[4][4];
#pragma unroll
            for (int mf = 0; mf < 4; mf++) {
                uint32_t addr = aBase + rowA[mf] * 128 +
                                (((kk * 2 + kcA) ^ (rowA[mf] & 7)) << 4);
                LDSM_X4(af[mf][0], af[mf][1], af[mf][2], af[mf][3], addr);
            }
            uint32_t bf[2][4];
#pragma unroll
            for (int nb2 = 0; nb2 < 2; nb2++) {
                uint32_t addr = bBase + rowB[nb2] * 128 +
                                (((kk * 2 + kcB) ^ (rowB[nb2] & 7)) << 4);
                LDSM_X4(bf[nb2][0], bf[nb2][1], bf[nb2][2], bf[nb2][3], addr);
            }
#pragma unroll
            for (int mf = 0; mf < 4; mf++)
#pragma unroll
                for (int nf = 0; nf < 4; nf++)
                    mma_fp16(acc[mf][nf], af[mf], &bf[nf >> 1][(nf & 1) * 2]);
        }
        __syncthreads();
    }

    // ---------------- epilogue ----------------
    if (MODE == 2) {
        const int tileid = blockIdx.x + blockIdx.y * 196;
        if (blockIdx.z == 0) {
            // write raw fp32 partial, publish flag
#pragma unroll
            for (int mf = 0; mf < 4; mf++)
#pragma unroll
                for (int nf = 0; nf < 4; nf++)
#pragma unroll
                    for (int half = 0; half < 2; half++) {
                        int grow = r0 + warp_m * 64 + mf * 16 + (lane >> 2) + half * 8;
                        int lcol = warp_n * 32 + nf * 8 + (lane & 3) * 2;
                        *(float2*)(partial + (size_t)grow * 256 + n0 + lcol) =
                            make_float2(acc[mf][nf][half * 2 + 0], acc[mf][nf][half * 2 + 1]);
                    }
            __threadfence();
            __syncthreads();
            if (tid == 0) atomicExch(&flags[tileid], 1);
            return;
        }
        // k-half 1: wait for partner (normally already done), add partial
        if (tid == 0) {
            while (atomicAdd(&flags[tileid], 0) == 0) {}
        }
        __syncthreads();
        __threadfence();
#pragma unroll
        for (int mf = 0; mf < 4; mf++)
#pragma unroll
            for (int nf = 0; nf < 4; nf++)
#pragma unroll
                for (int half = 0; half < 2; half++) {
                    int grow = r0 + warp_m * 64 + mf * 16 + (lane >> 2) + half * 8;
                    int lcol = warp_n * 32 + nf * 8 + (lane & 3) * 2;
                    float2 p = *(const float2*)(partial + (size_t)grow * 256 + n0 + lcol);
                    acc[mf][nf][half * 2 + 0] += p.x;
                    acc[mf][nf][half * 2 + 1] += p.y;
                }
        __syncthreads();
        float* stg = (float*)smem;  // 128 x 129 fp32 staging
#pragma unroll
        for (int mf = 0; mf < 4; mf++)
#pragma unroll
            for (int nf = 0; nf < 4; nf++)
#pragma unroll
                for (int half = 0; half < 2; half++) {
                    int rl = warp_m * 64 + mf * 16 + (lane >> 2) + half * 8;
                    int cl = warp_n * 32 + nf * 8 + (lane & 3) * 2;
                    stg[rl * 129 + cl] = fmaf(acc[mf][nf][half * 2 + 0], s_scale[cl], s_shift[cl]);
                    stg[rl * 129 + cl + 1] =
                        fmaf(acc[mf][nf][half * 2 + 1], s_scale[cl + 1], s_shift[cl + 1]);
                }
        __syncthreads();
        float* out = (float*)dstv;
#pragma unroll
        for (int cc = 0; cc < 16; cc++) {
            int c = wid * 16 + cc;
#pragma unroll
            for (int j = 0; j < 4; j++) {
                int i = lane + 32 * j;
                int r = r0 + i;
                int b = r / SPX;
                size_t o = ((size_t)(b * DIM + n0 + c)) * SPX + (r - b * SPX);
                out[o] = stg[i * 129 + c] + xres[o];
            }
        }
        return;
    }

    const int mw = r0 + warp_m * 64;
    const int nw = warp_n * 32;
    __half* dp_base = (__half*)dstv;
#pragma unroll
    for (int mf = 0; mf < 4; mf++) {
#pragma unroll
        for (int nf = 0; nf < 4; nf++) {
#pragma unroll
            for (int half = 0; half < 2; half++) {
                int grow = mw + mf * 16 + (lane >> 2) + half * 8;
                int lcol = nw + nf * 8 + (lane & 3) * 2;
                float v0 = fmaf(acc[mf][nf][half * 2 + 0], s_scale[lcol], s_shift[lcol]);
                float v1 = fmaf(acc[mf][nf][half * 2 + 1], s_scale[lcol + 1], s_shift[lcol + 1]);
                if (MODE == 1) {
                    v0 = 0.5f * v0 * (1.0f + erff(v0 * 0.70710678118654752f));
                    v1 = 0.5f * v1 * (1.0f + erff(v1 * 0.70710678118654752f));
                }
                __half2 hp;
                hp.x = __float2half_rn(v0);
                hp.y = __float2half_rn(v1);
                *(__half2*)(dp_base + (size_t)grow * DIM2 + n0 + lcol) = hp;
            }
        }
    }
}

// ---------------------------------------------------------------------------
extern "C" void kernel_launch(void* const* d_in, const int* in_sizes, int n_in,
                              void* d_out, int out_size) {
    const float* x   = (const float*)d_in[0];
    const float* w1  = (const float*)d_in[1];
    const float* b1  = (const float*)d_in[2];
    const float* g1  = (const float*)d_in[3];
    const float* be1 = (const float*)d_in[4];
    const float* m1  = (const float*)d_in[5];
    const float* v1  = (const float*)d_in[6];
    const float* wg  = (const float*)d_in[7];
    const float* bg  = (const float*)d_in[8];
    const float* gg  = (const float*)d_in[9];
    const float* beg = (const float*)d_in[10];
    const float* mg  = (const float*)d_in[11];
    const float* vg  = (const float*)d_in[12];
    const float* w2  = (const float*)d_in[13];
    const float* b2  = (const float*)d_in[14];
    const float* g2  = (const float*)d_in[15];
    const float* be2 = (const float*)d_in[16];
    const float* m2  = (const float*)d_in[17];
    const float* v2  = (const float*)d_in[18];

    __half *xTh, *cath, *gh, *w1h, *wgh, *w2h;
    float *sc1, *sh1, *scg, *shg, *sc2, *sh2;
    int* flags;
    cudaGetSymbolAddress((void**)&xTh, g_xTh);
    cudaGetSymbolAddress((void**)&cath, g_cath);
    cudaGetSymbolAddress((void**)&gh, g_gh);
    cudaGetSymbolAddress((void**)&w1h, g_w1h);
    cudaGetSymbolAddress((void**)&wgh, g_wgh);
    cudaGetSymbolAddress((void**)&w2h, g_w2h);
    cudaGetSymbolAddress((void**)&sc1, g_sc1);
    cudaGetSymbolAddress((void**)&sh1, g_sh1);
    cudaGetSymbolAddress((void**)&scg, g_scg);
    cudaGetSymbolAddress((void**)&shg, g_shg);
    cudaGetSymbolAddress((void**)&sc2, g_sc2);
    cudaGetSymbolAddress((void**)&sh2, g_sh2);
    cudaGetSymbolAddress((void**)&flags, g_flags);

    cudaFuncSetAttribute(fp16_gemm<0, 256, 256>, cudaFuncAttributeMaxDynamicSharedMemorySize, GSMEM);
    cudaFuncSetAttribute(fp16_gemm<1, 512, 512>, cudaFuncAttributeMaxDynamicSharedMemorySize, GSMEM);
    cudaFuncSetAttribute(fp16_gemm<2, 512, 256>, cudaFuncAttributeMaxDynamicSharedMemorySize, GSMEM);

    // transpose + weight pack + BN fold + flag reset (one launch, concurrent blocks)
    fused_prep<<<6721, 256>>>(x, w1, wg, w2, b1, g1, be1, m1, v1,
                              bg, gg, beg, mg, vg, b2, g2, be2, m2, v2);

    // fc1: cat[:, 0:256] = fp16(BN(x @ w1^T))
    fp16_gemm<0, 256, 256><<<dim3(196, 2), 256, GSMEM>>>(
        xTh, w1h, cath, nullptr, nullptr, nullptr, sc1, sh1);
    // MRConv4d -> cat[:, 256:512]
    minpass_kernel<<<dim3(56, 8, 4), 256>>>();
    combine_kernel<<<dim3(56, 8, 2), 256>>>();
    // g = fp16(GELU(BN(cat @ wg^T)))
    fp16_gemm<1, 512, 512><<<dim3(196, 4), 256, GSMEM>>>(
        cath, wgh, gh, nullptr, nullptr, nullptr, scg, shg);
    // fc2 split-K=2: out[B,256,S] = BN(g @ w2^T)^T + x
    // (k-half 0 = bids 0..391 writes partials into cath-as-fp32; k-half 1 reduces)
    fp16_gemm<2, 512, 256><<<dim3(196, 2, 2), 256, GSMEM>>>(
        gh, w2h, d_out, x, (float*)cath, flags, sc2, sh2);
}

// round 11
// speedup vs baseline: 1.7330x; 1.0163x over previous
#include <cuda_runtime.h>
#include <cuda_fp16.h>
#include <cstdint>

#define SPX 3136      // 56*56
#define BATCH 8
#define DIM 256
#define DIM2 512
#define ROWS_TOT (BATCH * SPX)   // 25088 = 196 * 128

// ---------------- scratch (static __device__, allocation-free) ----------------
__device__ __half g_xTh[(size_t)ROWS_TOT * DIM];     // fp16(x^T) [B*S, 256]
__device__ __half g_cath[(size_t)ROWS_TOT * DIM2];   // [B*S, 512] = [h | xj]; reused as fp32
                                                     // split-K partial scratch for fc2
__device__ __half g_gh[(size_t)ROWS_TOT * DIM2];     // gelu out [B*S, 512]
__device__ __half g_w1h[(size_t)DIM * DIM];          // fp16(w1) [256,256]
__device__ __half g_wgh[(size_t)DIM2 * DIM2];        // fp16(wg) [512,512]
__device__ __half g_w2h[(size_t)DIM * DIM2];         // fp16(w2) [256,512]
// packed two-smallest partials {m1,m2}:
__device__ float2 g_cmp[(size_t)BATCH * 56 * 2 * 2 * DIM];  // (b, x, y-half, parity, c)
__device__ float2 g_cmm[(size_t)BATCH * 56 * 2 * DIM];      // merged: (b, x, parity, c)
__device__ float2 g_rmp[(size_t)BATCH * 56 * 2 * 2 * DIM];  // (b, y, x-half, parity, c)
__device__ int g_flags[392];                          // fc2 split-K tile flags
__device__ float g_sc1[DIM], g_sh1[DIM];
__device__ float g_scg[DIM2], g_shg[DIM2];
__device__ float g_sc2[DIM], g_sh2[DIM];

// ---------------- PTX helpers (sm_80-generic only) ----------------
__device__ __forceinline__ uint32_t smem_u32(const void* p) {
    uint32_t a;
    asm("{ .reg .u64 t; cvta.to.shared.u64 t, %1; cvt.u32.u64 %0, t; }" : "=r"(a) : "l"(p));
    return a;
}
#define CP_ASYNC16(sm, gm) \
    asm volatile("cp.async.cg.shared.global [%0], [%1], 16;" :: "r"(sm), "l"(gm) : "memory")
#define CP_COMMIT() asm volatile("cp.async.commit_group;" ::: "memory")
#define CP_WAIT1() asm volatile("cp.async.wait_group 1;" ::: "memory")
#define CP_WAIT0() asm volatile("cp.async.wait_group 0;" ::: "memory")
#define LDSM_X4(r0, r1, r2, r3, addr)                                        \
    asm volatile("ldmatrix.sync.aligned.m8n8.x4.shared.b16 {%0,%1,%2,%3}, [%4];" \
                 : "=r"(r0), "=r"(r1), "=r"(r2), "=r"(r3) : "r"(addr))

__device__ __forceinline__ void mma_fp16(float* d, const uint32_t* a, const uint32_t* b) {
    asm volatile(
        "mma.sync.aligned.m16n8k16.row.col.f32.f16.f16.f32 "
        "{%0,%1,%2,%3}, {%4,%5,%6,%7}, {%8,%9}, {%0,%1,%2,%3};"
        : "+f"(d[0]), "+f"(d[1]), "+f"(d[2]), "+f"(d[3])
        : "r"(a[0]), "r"(a[1]), "r"(a[2]), "r"(a[3]), "r"(b[0]), "r"(b[1]));
}

// two-smallest merge (exact)
__device__ __forceinline__ float2 ts_merge2(float2 a, float2 b) {
    float2 r;
    r.x = fminf(a.x, b.x);
    r.y = fminf(fmaxf(a.x, b.x), fminf(a.y, b.y));
    return r;
}

// ---------------- fused transpose_in + prep + weight packing + flag reset ----------------
__global__ void __launch_bounds__(256) fused_prep(const float* __restrict__ x,
                          const float* __restrict__ w1, const float* __restrict__ wg,
                          const float* __restrict__ w2,
                          const float* __restrict__ b1, const float* __restrict__ g1,
                          const float* __restrict__ be1, const float* __restrict__ m1,
                          const float* __restrict__ v1,
                          const float* __restrict__ bg, const float* __restrict__ gg,
                          const float* __restrict__ beg, const float* __restrict__ mg,
                          const float* __restrict__ vg,
                          const float* __restrict__ b2, const float* __restrict__ g2,
                          const float* __restrict__ be2, const float* __restrict__ m2,
                          const float* __restrict__ v2) {
    int blk = blockIdx.x;
    if (blk < 6272) {
        __shared__ float t[32][33];
        int tx = threadIdx.x & 31, ty = threadIdx.x >> 5;
        int s0 = (blk % 98) * 32, c0 = ((blk / 98) & 7) * 32, b = blk / 784;
        const float* xp = x + ((size_t)b * DIM + c0) * SPX + s0;
        for (int i = ty; i < 32; i += 8) t[i][tx] = xp[(size_t)i * SPX + tx];
        __syncthreads();
        __half* op = g_xTh + ((size_t)(b * SPX + s0)) * DIM + c0;
        for (int i = ty; i < 32; i += 8)
            op[(size_t)i * DIM + tx] = __float2half_rn(t[tx][i]);
        return;
    }
    if (blk < 6720) {
        int pb = blk - 6272;
        int idx = pb * 256 + threadIdx.x;  // float4 index
        const float4* src;
        __half* dst;
        if (pb < 64) { src = (const float4*)w1; dst = g_w1h; }
        else if (pb < 320) { src = (const float4*)wg; dst = g_wgh; idx -= 16384; }
        else { src = (const float4*)w2; dst = g_w2h; idx -= 81920; }
        float4 f = src[idx];
        *(__half2*)(dst + (size_t)idx * 4) = __floats2half2_rn(f.x, f.y);
        *(__half2*)(dst + (size_t)idx * 4 + 2) = __floats2half2_rn(f.z, f.w);
        return;
    }
    int i = threadIdx.x;
    {
        float s = g1[i] / sqrtf(v1[i] + 1e-5f);
        g_sc1[i] = s; g_sh1[i] = (b1[i] - m1[i]) * s + be1[i];
        float s2 = g2[i] / sqrtf(v2[i] + 1e-5f);
        g_sc2[i] = s2; g_sh2[i] = (b2[i] - m2[i]) * s2 + be2[i];
    }
#pragma unroll
    for (int r = 0; r < 2; r++) {
        int j = i + r * 256;
        float sg = gg[j] / sqrtf(vg[j] + 1e-5f);
        g_scg[j] = sg; g_shg[j] = (bg[j] - mg[j]) * sg + beg[j];
    }
    g_flags[i] = 0;
    if (i + 256 < 392) g_flags[i + 256] = 0;
}

// ---------------- MRConv4d pass 1: col + row partial two-smallest (packed) ----------------
// grid (56, 8, 4): z<2 -> column pass (x = bx, y-half = z)
//                  z>=2 -> row pass (y = bx, x-half = z-2)
__global__ void __launch_bounds__(256) minpass_kernel() {
    int b = blockIdx.y, c = threadIdx.x;
    float a1e = 1e30f, a2e = 1e30f, a1o = 1e30f, a2o = 1e30f;
    if (blockIdx.z < 2) {
        int x = blockIdx.x, h = blockIdx.z;
        const __half* base = g_cath + ((size_t)(b * SPX + h * 28 * 56 + x)) * DIM2 + c;
        for (int i = 0; i < 28; i += 2) {
            float v = __half2float(base[(size_t)(i * 56) * DIM2]);
            if (v < a1e) { a2e = a1e; a1e = v; } else if (v < a2e) a2e = v;
            float w = __half2float(base[(size_t)((i + 1) * 56) * DIM2]);
            if (w < a1o) { a2o = a1o; a1o = w; } else if (w < a2o) a2o = w;
        }
        size_t o = (((size_t)(b * 56 + x) * 2 + h) * 2) * DIM + c;
        g_cmp[o] = make_float2(a1e, a2e);
        g_cmp[o + DIM] = make_float2(a1o, a2o);
    } else {
        int y = blockIdx.x, h = blockIdx.z - 2;
        const __half* base = g_cath + ((size_t)(b * SPX + y * 56 + h * 28)) * DIM2 + c;
        for (int i = 0; i < 28; i += 2) {
            float v = __half2float(base[(size_t)i * DIM2]);
            if (v < a1e) { a2e = a1e; a1e = v; } else if (v < a2e) a2e = v;
            float w = __half2float(base[(size_t)(i + 1) * DIM2]);
            if (w < a1o) { a2o = a1o; a1o = w; } else if (w < a2o) a2o = w;
        }
        size_t o = (((size_t)(b * 56 + y) * 2 + h) * 2) * DIM + c;
        g_rmp[o] = make_float2(a1e, a2e);
        g_rmp[o + DIM] = make_float2(a1o, a2o);
    }
}

// ---------------- MRConv4d pass 1.5: merge column-min y-halves ----------------
// grid (56 x, 8 b, 2 parity), 256 threads (c). One float2 out per thread.
__global__ void __launch_bounds__(256) merge_cm_kernel() {
    int x = blockIdx.x, b = blockIdx.y, p = blockIdx.z, c = threadIdx.x;
    size_t i0 = (((size_t)(b * 56 + x) * 2 + 0) * 2 + p) * DIM + c;
    size_t i1 = i0 + 2 * DIM;  // y-half 1
    g_cmm[(((size_t)(b * 56 + x)) * 2 + p) * DIM + c] = ts_merge2(g_cmp[i0], g_cmp[i1]);
}

// ---------------- MRConv4d pass 2: combine -> xj ----------------
// grid (56 y, 8 b, 4 x-quarter), 256 threads; 14 x's per block.
// Inner loop: 1 float2 cm load + 1 half load + 1 half store.
__global__ void __launch_bounds__(256) combine_kernel() {
    int y = blockIdx.x, b = blockIdx.y, xq = blockIdx.z, c = threadIdx.x;
    // merged row mins for this (b, y): parity 0 and 1
    float2 r[2];
    {
        size_t o0 = (((size_t)(b * 56 + y) * 2 + 0) * 2) * DIM + c;
        size_t o1 = o0 + 2 * DIM;
#pragma unroll
        for (int p = 0; p < 2; p++)
            r[p] = ts_merge2(g_rmp[o0 + p * DIM], g_rmp[o1 + p * DIM]);
    }
    int py = y & 1;
    const int x0 = xq * 14;
    const __half* hb = g_cath + ((size_t)(b * SPX + y * 56 + x0)) * DIM2 + c;
    __half* ob = g_cath + ((size_t)(b * SPX + y * 56 + x0)) * DIM2 + DIM + c;
    const float2* cmb = g_cmm + (((size_t)(b * 56 + x0)) * 2 + py) * DIM + c;
#pragma unroll 2
    for (int i = 0; i < 14; i++) {
        float v = __half2float(hb[(size_t)i * DIM2]);
        float2 cm = cmb[(size_t)i * 2 * DIM];
        float ec = (v == cm.x) ? cm.y : cm.x;
        float2 rr = r[i & 1];  // x0 even -> global parity = i&1
        float er = (v == rr.x) ? rr.y : rr.x;
        ob[(size_t)i * DIM2] = __float2half_rn(fmaxf(0.0f, v - fminf(ec, er)));
    }
}

// ---------------- fp16 mma.sync GEMM ----------------
// CTA 128x128, 8 warps (2m x 4n) of 64x32, BK=64, 256 threads, 2 CTAs/SM, 2-stage.
// MODE 0: BN -> fp16, row stride 512 (fc1)
// MODE 1: BN + exact GELU -> fp16, row stride 512 (gemm2)
// MODE 2: split-K fc2. blockIdx.z = k-half. half 0: raw fp32 partial + flag.
//         half 1: wait flag, add partial, BN + residual + transposed fp32 store.
#define GSMEM 66560
template <int MODE, int KSTRIDE, int KLEN>
__global__ void __launch_bounds__(256, 2)
fp16_gemm(const __half* __restrict__ Ag, const __half* __restrict__ Wg,
          void* __restrict__ dstv, const float* __restrict__ xres,
          float* __restrict__ partial, int* __restrict__ flags,
          const float* __restrict__ scale, const float* __restrict__ shift) {
    extern __shared__ __align__(1024) char smem[];
    __shared__ float s_scale[128], s_shift[128];
    const int tid = threadIdx.x, lane = tid & 31, wid = tid >> 5;
    const int warp_m = wid >> 2, warp_n = wid & 3;
    const int r0 = blockIdx.x * 128, n0 = blockIdx.y * 128;
    const int koff = (MODE == 2) ? (int)blockIdx.z * KLEN : 0;
    const uint32_t sb = smem_u32(smem);
    if (tid < 128) { s_scale[tid] = scale[n0 + tid]; s_shift[tid] = shift[n0 + tid]; }

    uint32_t loff[4];
    size_t aoff[4], boff[4];
#pragma unroll
    for (int i = 0; i < 4; i++) {
        int idx = tid + i * 256;
        int row = idx >> 3, c = idx & 7;
        loff[i] = row * 128 + ((c ^ (row & 7)) << 4);
        aoff[i] = (size_t)(r0 + row) * KSTRIDE + koff + c * 8;
        boff[i] = (size_t)(n0 + row) * KSTRIDE + koff + c * 8;
    }

    const int rowA[4] = {warp_m * 64 + 0 * 16 + (lane & 7) + ((lane >> 3) & 1) * 8,
                         warp_m * 64 + 1 * 16 + (lane & 7) + ((lane >> 3) & 1) * 8,
                         warp_m * 64 + 2 * 16 + (lane & 7) + ((lane >> 3) & 1) * 8,
                         warp_m * 64 + 3 * 16 + (lane & 7) + ((lane >> 3) & 1) * 8};
    const int kcA = lane >> 4;
    const int rowB[2] = {warp_n * 32 + 0 * 16 + (lane & 7) + ((lane >> 4) & 1) * 8,
                         warp_n * 32 + 1 * 16 + (lane & 7) + ((lane >> 4) & 1) * 8};
    const int kcB = (lane >> 3) & 1;

    float acc[4][4][4];
#pragma unroll
    for (int a = 0; a < 4; a++)
#pragma unroll
        for (int b = 0; b < 4; b++)
#pragma unroll
            for (int i = 0; i < 4; i++) acc[a][b][i] = 0.0f;

    constexpr int NS = KLEN >> 6;

    // prologue: stage 0 -> buf 0
#pragma unroll
    for (int i = 0; i < 4; i++) {
        CP_ASYNC16(sb + loff[i], Ag + aoff[i]);
        CP_ASYNC16(sb + 16384 + loff[i], Wg + boff[i]);
    }
    CP_COMMIT();

#pragma unroll
    for (int s = 0; s < NS; s++) {
        const uint32_t aBase = sb + (s & 1) * 32768;
        const uint32_t bBase = aBase + 16384;
        if (s + 1 < NS) {
            const uint32_t nb = sb + ((s + 1) & 1) * 32768;
            const size_t kadd = (size_t)(s + 1) * 64;
#pragma unroll
            for (int i = 0; i < 4; i++) {
                CP_ASYNC16(nb + loff[i], Ag + aoff[i] + kadd);
                CP_ASYNC16(nb + 16384 + loff[i], Wg + boff[i] + kadd);
            }
            CP_COMMIT();
            CP_WAIT1();
        } else {
            CP_WAIT0();
        }
        __syncthreads();

#pragma unroll
        for (int kk = 0; kk < 4; kk++) {
            uint32_t af[4][4];
#pragma unroll
            for (int mf = 0; mf < 4; mf++) {
                uint32_t addr = aBase + rowA[mf] * 128 +
                                (((kk * 2 + kcA) ^ (rowA[mf] & 7)) << 4);
                LDSM_X4(af[mf][0], af[mf][1], af[mf][2], af[mf][3], addr);
            }
            uint32_t bf[2][4];
#pragma unroll
            for (int nb2 = 0; nb2 < 2; nb2++) {
                uint32_t addr = bBase + rowB[nb2] * 128 +
                                (((kk * 2 + kcB) ^ (rowB[nb2] & 7)) << 4);
                LDSM_X4(bf[nb2][0], bf[nb2][1], bf[nb2][2], bf[nb2][3], addr);
            }
#pragma unroll
            for (int mf = 0; mf < 4; mf++)
#pragma unroll
                for (int nf = 0; nf < 4; nf++)
                    mma_fp16(acc[mf][nf], af[mf], &bf[nf >> 1][(nf & 1) * 2]);
        }
        __syncthreads();
    }

    // ---------------- epilogue ----------------
    if (MODE == 2) {
        const int tileid = blockIdx.x + blockIdx.y * 196;
        if (blockIdx.z == 0) {
#pragma unroll
            for (int mf = 0; mf < 4; mf++)
#pragma unroll
                for (int nf = 0; nf < 4; nf++)
#pragma unroll
                    for (int half = 0; half < 2; half++) {
                        int grow = r0 + warp_m * 64 + mf * 16 + (lane >> 2) + half * 8;
                        int lcol = warp_n * 32 + nf * 8 + (lane & 3) * 2;
                        *(float2*)(partial + (size_t)grow * 256 + n0 + lcol) =
                            make_float2(acc[mf][nf][half * 2 + 0], acc[mf][nf][half * 2 + 1]);
                    }
            __threadfence();
            __syncthreads();
            if (tid == 0) atomicExch(&flags[tileid], 1);
            return;
        }
        if (tid == 0) {
            while (atomicAdd(&flags[tileid], 0) == 0) {}
        }
        __syncthreads();
        __threadfence();
#pragma unroll
        for (int mf = 0; mf < 4; mf++)
#pragma unroll
            for (int nf = 0; nf < 4; nf++)
#pragma unroll
                for (int half = 0; half < 2; half++) {
                    int grow = r0 + warp_m * 64 + mf * 16 + (lane >> 2) + half * 8;
                    int lcol = warp_n * 32 + nf * 8 + (lane & 3) * 2;
                    float2 p = *(const float2*)(partial + (size_t)grow * 256 + n0 + lcol);
                    acc[mf][nf][half * 2 + 0] += p.x;
                    acc[mf][nf][half * 2 + 1] += p.y;
                }
        __syncthreads();
        float* stg = (float*)smem;  // 128 x 129 fp32 staging
#pragma unroll
        for (int mf = 0; mf < 4; mf++)
#pragma unroll
            for (int nf = 0; nf < 4; nf++)
#pragma unroll
                for (int half = 0; half < 2; half++) {
                    int rl = warp_m * 64 + mf * 16 + (lane >> 2) + half * 8;
                    int cl = warp_n * 32 + nf * 8 + (lane & 3) * 2;
                    stg[rl * 129 + cl] = fmaf(acc[mf][nf][half * 2 + 0], s_scale[cl], s_shift[cl]);
                    stg[rl * 129 + cl + 1] =
                        fmaf(acc[mf][nf][half * 2 + 1], s_scale[cl + 1], s_shift[cl + 1]);
                }
        __syncthreads();
        float* out = (float*)dstv;
#pragma unroll
        for (int cc = 0; cc < 16; cc++) {
            int c = wid * 16 + cc;
#pragma unroll
            for (int j = 0; j < 4; j++) {
                int i = lane + 32 * j;
                int r = r0 + i;
                int b = r / SPX;
                size_t o = ((size_t)(b * DIM + n0 + c)) * SPX + (r - b * SPX);
                out[o] = stg[i * 129 + c] + xres[o];
            }
        }
        return;
    }

    const int mw = r0 + warp_m * 64;
    const int nw = warp_n * 32;
    __half* dp_base = (__half*)dstv;
#pragma unroll
    for (int mf = 0; mf < 4; mf++) {
#pragma unroll
        for (int nf = 0; nf < 4; nf++) {
#pragma unroll
            for (int half = 0; half < 2; half++) {
                int grow = mw + mf * 16 + (lane >> 2) + half * 8;
                int lcol = nw + nf * 8 + (lane & 3) * 2;
                float v0 = fmaf(acc[mf][nf][half * 2 + 0], s_scale[lcol], s_shift[lcol]);
                float v1 = fmaf(acc[mf][nf][half * 2 + 1], s_scale[lcol + 1], s_shift[lcol + 1]);
                if (MODE == 1) {
                    v0 = 0.5f * v0 * (1.0f + erff(v0 * 0.70710678118654752f));
                    v1 = 0.5f * v1 * (1.0f + erff(v1 * 0.70710678118654752f));
                }
                __half2 hp;
                hp.x = __float2half_rn(v0);
                hp.y = __float2half_rn(v1);
                *(__half2*)(dp_base + (size_t)grow * DIM2 + n0 + lcol) = hp;
            }
        }
    }
}

// ---------------------------------------------------------------------------
extern "C" void kernel_launch(void* const* d_in, const int* in_sizes, int n_in,
                              void* d_out, int out_size) {
    const float* x   = (const float*)d_in[0];
    const float* w1  = (const float*)d_in[1];
    const float* b1  = (const float*)d_in[2];
    const float* g1  = (const float*)d_in[3];
    const float* be1 = (const float*)d_in[4];
    const float* m1  = (const float*)d_in[5];
    const float* v1  = (const float*)d_in[6];
    const float* wg  = (const float*)d_in[7];
    const float* bg  = (const float*)d_in[8];
    const float* gg  = (const float*)d_in[9];
    const float* beg = (const float*)d_in[10];
    const float* mg  = (const float*)d_in[11];
    const float* vg  = (const float*)d_in[12];
    const float* w2  = (const float*)d_in[13];
    const float* b2  = (const float*)d_in[14];
    const float* g2  = (const float*)d_in[15];
    const float* be2 = (const float*)d_in[16];
    const float* m2  = (const float*)d_in[17];
    const float* v2  = (const float*)d_in[18];

    __half *xTh, *cath, *gh, *w1h, *wgh, *w2h;
    float *sc1, *sh1, *scg, *shg, *sc2, *sh2;
    int* flags;
    cudaGetSymbolAddress((void**)&xTh, g_xTh);
    cudaGetSymbolAddress((void**)&cath, g_cath);
    cudaGetSymbolAddress((void**)&gh, g_gh);
    cudaGetSymbolAddress((void**)&w1h, g_w1h);
    cudaGetSymbolAddress((void**)&wgh, g_wgh);
    cudaGetSymbolAddress((void**)&w2h, g_w2h);
    cudaGetSymbolAddress((void**)&sc1, g_sc1);
    cudaGetSymbolAddress((void**)&sh1, g_sh1);
    cudaGetSymbolAddress((void**)&scg, g_scg);
    cudaGetSymbolAddress((void**)&shg, g_shg);
    cudaGetSymbolAddress((void**)&sc2, g_sc2);
    cudaGetSymbolAddress((void**)&sh2, g_sh2);
    cudaGetSymbolAddress((void**)&flags, g_flags);

    cudaFuncSetAttribute(fp16_gemm<0, 256, 256>, cudaFuncAttributeMaxDynamicSharedMemorySize, GSMEM);
    cudaFuncSetAttribute(fp16_gemm<1, 512, 512>, cudaFuncAttributeMaxDynamicSharedMemorySize, GSMEM);
    cudaFuncSetAttribute(fp16_gemm<2, 512, 256>, cudaFuncAttributeMaxDynamicSharedMemorySize, GSMEM);

    // transpose + weight pack + BN fold + flag reset (one launch, concurrent blocks)
    fused_prep<<<6721, 256>>>(x, w1, wg, w2, b1, g1, be1, m1, v1,
                              bg, gg, beg, mg, vg, b2, g2, be2, m2, v2);

    // fc1: cat[:, 0:256] = fp16(BN(x @ w1^T))
    fp16_gemm<0, 256, 256><<<dim3(196, 2), 256, GSMEM>>>(
        xTh, w1h, cath, nullptr, nullptr, nullptr, sc1, sh1);
    // MRConv4d -> cat[:, 256:512]
    minpass_kernel<<<dim3(56, 8, 4), 256>>>();
    merge_cm_kernel<<<dim3(56, 8, 2), 256>>>();
    combine_kernel<<<dim3(56, 8, 4), 256>>>();
    // g = fp16(GELU(BN(cat @ wg^T)))
    fp16_gemm<1, 512, 512><<<dim3(196, 4), 256, GSMEM>>>(
        cath, wgh, gh, nullptr, nullptr, nullptr, scg, shg);
    // fc2 split-K=2: out[B,256,S] = BN(g @ w2^T)^T + x
    fp16_gemm<2, 512, 256><<<dim3(196, 2, 2), 256, GSMEM>>>(
        gh, w2h, d_out, x, (float*)cath, flags, sc2, sh2);
}